// round 10
// baseline (speedup 1.0000x reference)
#include <cuda_runtime.h>
#include <cuda_bf16.h>
#include <math.h>
#include <stdint.h>

#define NB 8
#define TSEQ 2048
#define DM 512
#define NH 8
#define HD 64
#define MTOT (NB * TSEQ)          // 16384
#define EQKV (3 * DM)             // 1536

#define QT 64

// ---- flash attention smem layout (bytes) ----
#define AQ_OFF   0                         // 64 x 200 bf16 (Qcat), pitch 400B
#define AK_OFF(s) (25600 + (s) * 43008)    // 64 x 200 bf16 K tile, pitch 400B
#define AV_OFF(s) (AK_OFF(s) + 25600)      // 64 x 136 bf16 V tile (hi|lo), pitch 272B
#define ARMAX_OFF 111616                   // 2 x 64 fp32
#define ASUM_OFF  112128                   // 2 x 64 fp32
#define AO_OFF    25600                    // 64 x 64 fp32 exchange (overlays stage0 K)
#define AFL_SMEM  112640

// GEMM operand row: 2048 bytes = [fp8 1024 | bf16 1024]
//  activations: fp8 = [lo*2^9 | full],  bf16 = hi
//  weights:     fp8 = [full*2^4 | lo*2^13], bf16 = hi
// C = 2^-13 * fp8GEMM + bf16GEMM  (= AlB + ABl + AhBh ≈ AB to ~2^-13)
#define GROW 2048

// ---------------- scratch (device globals) ----------------------------------
__device__ float g_qkv[(size_t)MTOT * EQKV];
__device__ float g_cos[TSEQ * 32];
__device__ float g_sin[TSEQ * 32];
__device__ __nv_bfloat16 g_Qc[(size_t)NB * NH * TSEQ * 192];  // [Qh|Ql|Qh]
__device__ __nv_bfloat16 g_Kc[(size_t)NB * NH * TSEQ * 192];  // [Kh|Kh|Kl]
__device__ __nv_bfloat16 g_Vth[(size_t)NB * NH * HD * TSEQ];  // V^T hi [d][t]
__device__ __nv_bfloat16 g_Vtl[(size_t)NB * NH * HD * TSEQ];  // V^T lo [d][t]
__device__ uint8_t g_xcat8[(size_t)MTOT * GROW];
__device__ uint8_t g_acat8[(size_t)MTOT * GROW];              // attention out
__device__ uint8_t g_wqcat8[(size_t)EQKV * GROW];
__device__ uint8_t g_wocat8[(size_t)DM * GROW];

// ---------------- helpers ----------------------------------------------------
__device__ __forceinline__ uint32_t smem_u32(const void* p) {
    uint32_t a;
    asm("{ .reg .u64 t; cvta.to.shared.u64 t, %1; cvt.u32.u64 %0, t; }"
        : "=r"(a) : "l"(p));
    return a;
}

__device__ __forceinline__ void cp16(uint32_t dst, const void* src) {
    asm volatile("cp.async.cg.shared.global [%0], [%1], 16;"
                 :: "r"(dst), "l"(src) : "memory");
}

__device__ __forceinline__ void ldsm4(uint32_t& r0, uint32_t& r1,
                                      uint32_t& r2, uint32_t& r3, uint32_t addr) {
    asm volatile("ldmatrix.sync.aligned.m8n8.x4.shared.b16 {%0,%1,%2,%3}, [%4];"
                 : "=r"(r0), "=r"(r1), "=r"(r2), "=r"(r3) : "r"(addr));
}

__device__ __forceinline__ void mma16816(float* c, const uint32_t* a,
                                         uint32_t b0, uint32_t b1) {
    asm volatile(
        "mma.sync.aligned.m16n8k16.row.col.f32.bf16.bf16.f32 "
        "{%0,%1,%2,%3}, {%4,%5,%6,%7}, {%8,%9}, {%0,%1,%2,%3};"
        : "+f"(c[0]), "+f"(c[1]), "+f"(c[2]), "+f"(c[3])
        : "r"(a[0]), "r"(a[1]), "r"(a[2]), "r"(a[3]), "r"(b0), "r"(b1));
}

__device__ __forceinline__ void mma16832f8(float* c, const uint32_t* a,
                                           uint32_t b0, uint32_t b1) {
    asm volatile(
        "mma.sync.aligned.m16n8k32.row.col.f32.e4m3.e4m3.f32 "
        "{%0,%1,%2,%3}, {%4,%5,%6,%7}, {%8,%9}, {%0,%1,%2,%3};"
        : "+f"(c[0]), "+f"(c[1]), "+f"(c[2]), "+f"(c[3])
        : "r"(a[0]), "r"(a[1]), "r"(a[2]), "r"(a[3]), "r"(b0), "r"(b1));
}

__device__ __forceinline__ uint16_t e4m3x2(float hi, float lo) {
    uint16_t r;
    asm("cvt.rn.satfinite.e4m3x2.f32 %0, %1, %2;" : "=h"(r) : "f"(hi), "f"(lo));
    return r;   // low byte <- lo, high byte <- hi
}

__device__ __forceinline__ uint16_t bfbits(__nv_bfloat16 b) {
    return *reinterpret_cast<uint16_t*>(&b);
}

__device__ __forceinline__ uint32_t pack2(float a, float b) {
    __nv_bfloat16 ha = __float2bfloat16(a), hb = __float2bfloat16(b);
    return (uint32_t)bfbits(ha) | ((uint32_t)bfbits(hb) << 16);
}

// pack the bf16 lo-residuals of a,b
__device__ __forceinline__ uint32_t pack2lo(float a, float b) {
    __nv_bfloat16 ha = __float2bfloat16(a), hb = __float2bfloat16(b);
    __nv_bfloat16 la = __float2bfloat16(a - __bfloat162float(ha));
    __nv_bfloat16 lb = __float2bfloat16(b - __bfloat162float(hb));
    return (uint32_t)bfbits(la) | ((uint32_t)bfbits(lb) << 16);
}

__device__ __forceinline__ void split1(float x, __nv_bfloat16& h, __nv_bfloat16& l) {
    h = __float2bfloat16(x);
    l = __float2bfloat16(x - __bfloat162float(h));
}

// ---------------- bf16+fp8 mma.sync GEMM (3-stage pipeline, occ 2) ----------
#define SROW 40
#define STAGE_BYTES (128 * SROW * 2)   // 10240 (80B pitch, 64B used/row)

template <bool BIAS>
__global__ __launch_bounds__(256, 2)
void gemm_mma(const uint8_t* __restrict__ A, const uint8_t* __restrict__ B,
              const float* __restrict__ bias, float* __restrict__ C, int N) {
    __shared__ __nv_bfloat16 sA[3][128 * SROW];
    __shared__ __nv_bfloat16 sB[3][128 * SROW];

    const int tid = threadIdx.x;
    const int lid = tid & 31;
    const int wid = tid >> 5;
    const int wm = wid >> 2;
    const int wn = wid & 3;
    const int m0 = blockIdx.y * 128;
    const int n0 = blockIdx.x * 128;
    const uint32_t sAb = smem_u32(sA);
    const uint32_t sBb = smem_u32(sB);

    float acc[4][4][4];
#pragma unroll
    for (int i = 0; i < 4; i++)
#pragma unroll
        for (int j = 0; j < 4; j++)
#pragma unroll
            for (int q = 0; q < 4; q++) acc[i][j][q] = 0.f;

#define PREFETCH(stage, kt_)                                                    \
    {                                                                           \
        _Pragma("unroll")                                                       \
        for (int i = 0; i < 2; ++i) {                                           \
            int u = tid + i * 256;                                              \
            int row = u >> 2, c = u & 3;                                        \
            cp16(sAb + (stage) * STAGE_BYTES + row * 80 + c * 16,               \
                 A + (size_t)(m0 + row) * GROW + (kt_) * 64 + c * 16);          \
            cp16(sBb + (stage) * STAGE_BYTES + row * 80 + c * 16,               \
                 B + (size_t)(n0 + row) * GROW + (kt_) * 64 + c * 16);          \
        }                                                                       \
        asm volatile("cp.async.commit_group;" ::: "memory");                    \
    }

#define INNER(MMA_FN)                                                           \
    {                                                                           \
        _Pragma("unroll")                                                       \
        for (int ks = 0; ks < 32; ks += 16) {                                   \
            uint32_t a[4][4], b[2][4];                                          \
            _Pragma("unroll")                                                   \
            for (int mi = 0; mi < 4; ++mi) {                                    \
                int row = wm * 64 + mi * 16 + (lid & 7) + ((lid >> 3) & 1) * 8; \
                int ke = ks + ((lid >> 4) << 3);                                \
                ldsm4(a[mi][0], a[mi][1], a[mi][2], a[mi][3],                   \
                      sa + (uint32_t)(row * SROW + ke) * 2);                    \
            }                                                                   \
            _Pragma("unroll")                                                   \
            for (int nb = 0; nb < 2; ++nb) {                                    \
                int nn = wn * 32 + nb * 16 + (lid & 7) + ((lid >> 4) & 1) * 8;  \
                int ke = ks + (((lid >> 3) & 1) << 3);                          \
                ldsm4(b[nb][0], b[nb][1], b[nb][2], b[nb][3],                   \
                      sb + (uint32_t)(nn * SROW + ke) * 2);                     \
            }                                                                   \
            _Pragma("unroll")                                                   \
            for (int mi = 0; mi < 4; ++mi)                                      \
                _Pragma("unroll")                                               \
                for (int nf = 0; nf < 4; ++nf)                                  \
                    MMA_FN(acc[mi][nf], a[mi],                                  \
                           b[nf >> 1][(nf & 1) * 2], b[nf >> 1][(nf & 1) * 2 + 1]); \
        }                                                                       \
    }

    const int NKT = 32;   // 16 fp8 chunks (corrections) + 16 bf16 chunks (main)
    PREFETCH(0, 0);
    PREFETCH(1, 1);

    int stage = 0;
    for (int kt = 0; kt < NKT; ++kt) {
        if (kt + 2 < NKT) {
            int ps = stage + 2; if (ps >= 3) ps -= 3;
            PREFETCH(ps, kt + 2);
            asm volatile("cp.async.wait_group 2;" ::: "memory");
        } else if (kt + 1 < NKT) {
            asm volatile("cp.async.wait_group 1;" ::: "memory");
        } else {
            asm volatile("cp.async.wait_group 0;" ::: "memory");
        }
        __syncthreads();

        const uint32_t sa = sAb + stage * STAGE_BYTES;
        const uint32_t sb = sBb + stage * STAGE_BYTES;

        if (kt < 16) {
            INNER(mma16832f8);
            if (kt == 15) {
                const float s = 1.0f / 8192.0f;   // 2^-13
#pragma unroll
                for (int i = 0; i < 4; i++)
#pragma unroll
                    for (int j = 0; j < 4; j++)
#pragma unroll
                        for (int q = 0; q < 4; q++) acc[i][j][q] *= s;
            }
        } else {
            INNER(mma16816);
        }
        __syncthreads();
        ++stage; if (stage == 3) stage = 0;
    }

    const int r = lid >> 2;
    const int cc = (lid & 3) * 2;
#pragma unroll
    for (int mi = 0; mi < 4; ++mi) {
#pragma unroll
        for (int nf = 0; nf < 4; ++nf) {
            int row = m0 + wm * 64 + mi * 16 + r;
            int col = n0 + wn * 32 + nf * 8 + cc;
            float bx = 0.f, by = 0.f;
            if (BIAS) { bx = bias[col]; by = bias[col + 1]; }
            float2 v0 = make_float2(acc[mi][nf][0] + bx, acc[mi][nf][1] + by);
            float2 v1 = make_float2(acc[mi][nf][2] + bx, acc[mi][nf][3] + by);
            *(float2*)(C + (size_t)row * N + col) = v0;
            *(float2*)(C + (size_t)(row + 8) * N + col) = v1;
        }
    }
#undef PREFETCH
#undef INNER
}

// ---------------- fp32 -> fp8/bf16 concat split ------------------------------
// MODE 0 activation: fp8 [lo*2^9 | full], bf16 hi
// MODE 1 weight:     fp8 [full*2^4 | lo*2^13], bf16 hi
template <int MODE>
__global__ void split_cat_kernel(const float* __restrict__ src,
                                 uint8_t* __restrict__ dst, int total4) {
    int i = blockIdx.x * blockDim.x + threadIdx.x;
    if (i >= total4) return;
    int row = i >> 7;          // 128 float4 per 512-float row
    int c = (i & 127) * 4;
    float4 v = ((const float4*)src)[i];
    float x0 = v.x, x1 = v.y, x2 = v.z, x3 = v.w;
    __nv_bfloat16 h0 = __float2bfloat16(x0), h1 = __float2bfloat16(x1);
    __nv_bfloat16 h2 = __float2bfloat16(x2), h3 = __float2bfloat16(x3);
    float l0 = x0 - __bfloat162float(h0), l1 = x1 - __bfloat162float(h1);
    float l2 = x2 - __bfloat162float(h2), l3 = x3 - __bfloat162float(h3);

    uint8_t* base = dst + (size_t)row * GROW;
    uint32_t w0 = (uint32_t)bfbits(h0) | ((uint32_t)bfbits(h1) << 16);
    uint32_t w1 = (uint32_t)bfbits(h2) | ((uint32_t)bfbits(h3) << 16);
    *(uint2*)(base + 1024 + 2 * c) = make_uint2(w0, w1);

    uint16_t p0, p1, q0, q1;
    if (MODE == 0) {
        p0 = e4m3x2(l1 * 512.f, l0 * 512.f);
        p1 = e4m3x2(l3 * 512.f, l2 * 512.f);
        q0 = e4m3x2(x1, x0);
        q1 = e4m3x2(x3, x2);
    } else {
        p0 = e4m3x2(x1 * 16.f, x0 * 16.f);
        p1 = e4m3x2(x3 * 16.f, x2 * 16.f);
        q0 = e4m3x2(l1 * 8192.f, l0 * 8192.f);
        q1 = e4m3x2(l3 * 8192.f, l2 * 8192.f);
    }
    *(uint32_t*)(base + c)       = (uint32_t)p0 | ((uint32_t)p1 << 16);
    *(uint32_t*)(base + 512 + c) = (uint32_t)q0 | ((uint32_t)q1 << 16);
}

// ---------------- RoPE table ------------------------------------------------
__global__ void rope_table_kernel() {
    int idx = blockIdx.x * blockDim.x + threadIdx.x;
    if (idx >= TSEQ * 32) return;
    int t = idx >> 5;
    int j = idx & 31;
    double inv = exp(-log(10000.0) * (double)j / 32.0);
    float ang = (float)t * (float)inv;
    g_cos[idx] = (float)cos((double)ang);
    g_sin[idx] = (float)sin((double)ang);
}

// ---------------- RoPE + split-concat Q/K -----------------------------------
__global__ void rope_qk_kernel() {
    int idx = blockIdx.x * blockDim.x + threadIdx.x;
    const int total = NB * TSEQ * NH * 32;
    if (idx >= total) return;
    int j = idx & 31;
    int h = (idx >> 5) & 7;
    int t = (idx >> 8) & (TSEQ - 1);
    int n = idx >> 19;
    int nh = n * NH + h;

    const float* base = g_qkv + (size_t)(n * TSEQ + t) * EQKV;
    float c = g_cos[t * 32 + j];
    float s = g_sin[t * 32 + j];

    float q1 = base[h * HD + j];
    float q2 = base[h * HD + j + 32];
    float k1 = base[DM + h * HD + j];
    float k2 = base[DM + h * HD + j + 32];

    float q1r = q1 * c - q2 * s;
    float q2r = q2 * c + q1 * s;
    float k1r = k1 * c - k2 * s;
    float k2r = k2 * c + k1 * s;

    __nv_bfloat16 h1, l1, h2, l2;
    __nv_bfloat16* qrow = g_Qc + ((size_t)nh * TSEQ + t) * 192;
    split1(q1r, h1, l1); split1(q2r, h2, l2);
    qrow[j]      = h1; qrow[64 + j] = l1; qrow[128 + j] = h1;
    qrow[32 + j] = h2; qrow[96 + j] = l2; qrow[160 + j] = h2;

    __nv_bfloat16* krow = g_Kc + ((size_t)nh * TSEQ + t) * 192;
    split1(k1r, h1, l1); split1(k2r, h2, l2);
    krow[j]      = h1; krow[64 + j] = h1; krow[128 + j] = l1;
    krow[32 + j] = h2; krow[96 + j] = h2; krow[160 + j] = l2;
}

// ---------------- V transpose + split ---------------------------------------
__global__ void vtrans_kernel() {
    __shared__ __nv_bfloat16 svh[64 * 33];
    __shared__ __nv_bfloat16 svl[64 * 33];
    const int tid = threadIdx.x;
    const int nh = blockIdx.y;
    const int n = nh >> 3, h = nh & 7;
    const int t0 = blockIdx.x * 32;

#pragma unroll
    for (int i = 0; i < 8; i++) {
        int e = tid + i * 256;
        int tl = e >> 6, d = e & 63;
        float v = g_qkv[(size_t)(n * TSEQ + t0 + tl) * EQKV + 2 * DM + h * HD + d];
        __nv_bfloat16 hb, lb;
        split1(v, hb, lb);
        svh[d * 33 + tl] = hb;
        svl[d * 33 + tl] = lb;
    }
    __syncthreads();
#pragma unroll
    for (int i = 0; i < 8; i++) {
        int e = tid + i * 256;
        int d = e >> 5, tl = e & 31;
        size_t o = ((size_t)nh * HD + d) * TSEQ + t0 + tl;
        g_Vth[o] = svh[d * 33 + tl];
        g_Vtl[o] = svl[d * 33 + tl];
    }
}

// ---------------- flash-style banded attention ------------------------------
// CTA per (n*NH+h, 64-q tile). 8 warps: wr = row slice (4), wc = j-half (2).
__global__ __launch_bounds__(256, 2)
void attn_flash_kernel() {
    extern __shared__ char smc[];
    const uint32_t sb = smem_u32(smc);
    float* sRMax = (float*)(smc + ARMAX_OFF);   // [2][64]
    float* sSum  = (float*)(smc + ASUM_OFF);    // [2][64]
    float* sO    = (float*)(smc + AO_OFF);      // [64][64]

    const int tid = threadIdx.x;
    const int lid = tid & 31, wid = tid >> 5;
    const int wr = wid & 3, wc = wid >> 2;
    const int q0 = blockIdx.x * QT;
    const int nh = blockIdx.y;
    const int n = nh >> 3, h = nh & 7;
    const int ks = q0 - 128;
    const float scale = 0.125f;

    const int rlo = wr * 16 + (lid >> 2);
    const int rhi = rlo + 8;

    // ---- Q tile ----
#pragma unroll
    for (int i = 0; i < 6; i++) {
        int u = tid + i * 256;
        int r = u / 24, c = u % 24;
        cp16(sb + AQ_OFF + r * 400 + c * 16,
             g_Qc + ((size_t)nh * TSEQ + q0 + r) * 192 + c * 8);
    }

#define ISSUE_KV(jt_, st_)                                                      \
    {                                                                           \
        _Pragma("unroll")                                                       \
        for (int i = 0; i < 6; i++) {                                           \
            int u = tid + i * 256;                                              \
            int r = u / 24, c = u % 24;                                         \
            int j = ks + (jt_) * 64 + r;                                        \
            j = j < 0 ? 0 : (j > TSEQ - 1 ? TSEQ - 1 : j);                      \
            cp16(sb + AK_OFF(st_) + r * 400 + c * 16,                           \
                 g_Kc + ((size_t)nh * TSEQ + j) * 192 + c * 8);                 \
        }                                                                       \
        _Pragma("unroll")                                                       \
        for (int i = 0; i < 4; i++) {                                           \
            int u = tid + i * 256;                                              \
            int r = u >> 4, c = u & 15;                                         \
            int jb = ks + (jt_) * 64 + (c & 7) * 8;                             \
            jb = jb < 0 ? 0 : (jb > TSEQ - 8 ? TSEQ - 8 : jb);                  \
            const __nv_bfloat16* vs = (c < 8) ? g_Vth : g_Vtl;                  \
            cp16(sb + AV_OFF(st_) + r * 272 + c * 16,                           \
                 vs + ((size_t)nh * HD + r) * TSEQ + jb);                       \
        }                                                                       \
        asm volatile("cp.async.commit_group;" ::: "memory");                    \
    }

    ISSUE_KV(0, 0);

    float oacc[8][4];
#pragma unroll
    for (int i = 0; i < 8; i++)
#pragma unroll
        for (int q = 0; q < 4; q++) oacc[i][q] = 0.f;
    float m0 = -1e30f, m1 = -1e30f;
    float sum0 = 0.f, sum1 = 0.f;

    for (int jt = 0; jt < 5; ++jt) {
        const int st = jt & 1;
        if (jt < 4) {
            ISSUE_KV(jt + 1, st ^ 1);
            asm volatile("cp.async.wait_group 1;" ::: "memory");
        } else {
            asm volatile("cp.async.wait_group 0;" ::: "memory");
        }
        __syncthreads();

        // ---- S = Qcat · Kcat^T ----
        float sacc[4][4];
#pragma unroll
        for (int i = 0; i < 4; i++)
#pragma unroll
            for (int q = 0; q < 4; q++) sacc[i][q] = 0.f;

        const uint32_t kb = sb + AK_OFF(st);
#pragma unroll
        for (int k16 = 0; k16 < 12; ++k16) {
            uint32_t a[4], b[2][4];
            {
                int row = wr * 16 + (lid & 7) + ((lid >> 3) & 1) * 8;
                int ke = k16 * 16 + ((lid >> 4) << 3);
                ldsm4(a[0], a[1], a[2], a[3], sb + AQ_OFF + row * 400 + ke * 2);
            }
#pragma unroll
            for (int nb = 0; nb < 2; ++nb) {
                int nn = wc * 32 + nb * 16 + (lid & 7) + ((lid >> 4) & 1) * 8;
                int ke = k16 * 16 + (((lid >> 3) & 1) << 3);
                ldsm4(b[nb][0], b[nb][1], b[nb][2], b[nb][3], kb + nn * 400 + ke * 2);
            }
#pragma unroll
            for (int nf = 0; nf < 4; ++nf)
                mma16816(sacc[nf], a, b[nf >> 1][(nf & 1) * 2],
                         b[nf >> 1][(nf & 1) * 2 + 1]);
        }

        // ---- mask + scale ----
#pragma unroll
        for (int nf = 0; nf < 4; ++nf) {
#pragma unroll
            for (int e = 0; e < 2; ++e) {
                int j = ks + jt * 64 + wc * 32 + nf * 8 + 2 * (lid & 3) + e;
                int d0 = j - (q0 + rlo);
                int d1 = j - (q0 + rhi);
                bool in = (j >= 0) && (j < TSEQ);
                sacc[nf][e]     = (in && d0 >= -127 && d0 <= 128)
                                  ? sacc[nf][e] * scale : -1e30f;
                sacc[nf][2 + e] = (in && d1 >= -127 && d1 <= 128)
                                  ? sacc[nf][2 + e] * scale : -1e30f;
            }
        }

        // ---- online softmax ----
        float mx0 = sacc[0][0], mx1 = sacc[0][2];
#pragma unroll
        for (int nf = 0; nf < 4; ++nf) {
            mx0 = fmaxf(mx0, fmaxf(sacc[nf][0], sacc[nf][1]));
            mx1 = fmaxf(mx1, fmaxf(sacc[nf][2], sacc[nf][3]));
        }
        mx0 = fmaxf(mx0, __shfl_xor_sync(0xffffffffu, mx0, 1));
        mx0 = fmaxf(mx0, __shfl_xor_sync(0xffffffffu, mx0, 2));
        mx1 = fmaxf(mx1, __shfl_xor_sync(0xffffffffu, mx1, 1));
        mx1 = fmaxf(mx1, __shfl_xor_sync(0xffffffffu, mx1, 2));
        if ((lid & 3) == 0) {
            sRMax[wc * 64 + rlo] = mx0;
            sRMax[wc * 64 + rhi] = mx1;
        }
        __syncthreads();
        float nm0 = fmaxf(m0, fmaxf(sRMax[rlo], sRMax[64 + rlo]));
        float nm1 = fmaxf(m1, fmaxf(sRMax[rhi], sRMax[64 + rhi]));
        float f0 = __expf(m0 - nm0);
        float f1 = __expf(m1 - nm1);
        m0 = nm0; m1 = nm1;
        sum0 *= f0; sum1 *= f1;
#pragma unroll
        for (int i = 0; i < 8; i++) {
            oacc[i][0] *= f0; oacc[i][1] *= f0;
            oacc[i][2] *= f1; oacc[i][3] *= f1;
        }

        // ---- P = exp(S - m) -> bf16 hi/lo A-frags ----
        uint32_t ph[2][4], pl[2][4];
#pragma unroll
        for (int nf = 0; nf < 4; ++nf) {
            float p0 = __expf(sacc[nf][0] - nm0);
            float p1 = __expf(sacc[nf][1] - nm0);
            float p2 = __expf(sacc[nf][2] - nm1);
            float p3 = __expf(sacc[nf][3] - nm1);
            sum0 += p0 + p1;
            sum1 += p2 + p3;
            int b = nf >> 1;
            int o = (nf & 1) * 2;
            ph[b][o]     = pack2(p0, p1);
            ph[b][o + 1] = pack2(p2, p3);
            pl[b][o]     = pack2lo(p0, p1);
            pl[b][o + 1] = pack2lo(p2, p3);
        }

        // ---- O += Pcat · Vcat ----
        const uint32_t vb = sb + AV_OFF(st);
#pragma unroll
        for (int b = 0; b < 2; ++b) {
            int kcol = wc * 32 + b * 16;
            uint32_t v[4][4];
#pragma unroll
            for (int dnb = 0; dnb < 4; ++dnb) {
                int nn = dnb * 16 + (lid & 7) + ((lid >> 4) & 1) * 8;
                int kk = kcol + (((lid >> 3) & 1) << 3);
                ldsm4(v[dnb][0], v[dnb][1], v[dnb][2], v[dnb][3],
                      vb + nn * 272 + kk * 2);          // V hi
            }
#pragma unroll
            for (int n8 = 0; n8 < 8; ++n8) {
                mma16816(oacc[n8], ph[b], v[n8 >> 1][(n8 & 1) * 2],
                         v[n8 >> 1][(n8 & 1) * 2 + 1]);
                mma16816(oacc[n8], pl[b], v[n8 >> 1][(n8 & 1) * 2],
                         v[n8 >> 1][(n8 & 1) * 2 + 1]);
            }
#pragma unroll
            for (int dnb = 0; dnb < 4; ++dnb) {
                int nn = dnb * 16 + (lid & 7) + ((lid >> 4) & 1) * 8;
                int kk = kcol + (((lid >> 3) & 1) << 3);
                ldsm4(v[dnb][0], v[dnb][1], v[dnb][2], v[dnb][3],
                      vb + nn * 272 + 128 + kk * 2);    // V lo
            }
#pragma unroll
            for (int n8 = 0; n8 < 8; ++n8)
                mma16816(oacc[n8], ph[b], v[n8 >> 1][(n8 & 1) * 2],
                         v[n8 >> 1][(n8 & 1) * 2 + 1]);
        }
        __syncthreads();
    }
#undef ISSUE_KV

    // ---- combine halves, normalize, write GEMM2 operand format ----
    sum0 += __shfl_xor_sync(0xffffffffu, sum0, 1);
    sum0 += __shfl_xor_sync(0xffffffffu, sum0, 2);
    sum1 += __shfl_xor_sync(0xffffffffu, sum1, 1);
    sum1 += __shfl_xor_sync(0xffffffffu, sum1, 2);
    if ((lid & 3) == 0) {
        sSum[wc * 64 + rlo] = sum0;
        sSum[wc * 64 + rhi] = sum1;
    }
    if (wc == 1) {
#pragma unroll
        for (int i = 0; i < 8; i++) {
            int d = i * 8 + 2 * (lid & 3);
            sO[rlo * 64 + d] = oacc[i][0];
            sO[rlo * 64 + d + 1] = oacc[i][1];
            sO[rhi * 64 + d] = oacc[i][2];
            sO[rhi * 64 + d + 1] = oacc[i][3];
        }
    }
    __syncthreads();
    if (wc == 0) {
        float inv0 = 1.f / (sSum[rlo] + sSum[64 + rlo]);
        float inv1 = 1.f / (sSum[rhi] + sSum[64 + rhi]);
        uint8_t* rowA = g_acat8 + ((size_t)(n * TSEQ) + q0 + rlo) * GROW;
        uint8_t* rowB = g_acat8 + ((size_t)(n * TSEQ) + q0 + rhi) * GROW;
#pragma unroll
        for (int i = 0; i < 8; i++) {
            int d = i * 8 + 2 * (lid & 3);
            int col = h * HD + d;
            float v0 = (oacc[i][0] + sO[rlo * 64 + d]) * inv0;
            float v1 = (oacc[i][1] + sO[rlo * 64 + d + 1]) * inv0;
            float v2 = (oacc[i][2] + sO[rhi * 64 + d]) * inv1;
            float v3 = (oacc[i][3] + sO[rhi * 64 + d + 1]) * inv1;
            __nv_bfloat16 h0 = __float2bfloat16(v0), h1 = __float2bfloat16(v1);
            __nv_bfloat16 h2 = __float2bfloat16(v2), h3 = __float2bfloat16(v3);
            float l0 = v0 - __bfloat162float(h0), l1 = v1 - __bfloat162float(h1);
            float l2 = v2 - __bfloat162float(h2), l3 = v3 - __bfloat162float(h3);
            // bf16 hi
            *(uint32_t*)(rowA + 1024 + 2 * col) =
                (uint32_t)bfbits(h0) | ((uint32_t)bfbits(h1) << 16);
            *(uint32_t*)(rowB + 1024 + 2 * col) =
                (uint32_t)bfbits(h2) | ((uint32_t)bfbits(h3) << 16);
            // fp8: [lo*2^9 | full]
            *(uint16_t*)(rowA + col)       = e4m3x2(l1 * 512.f, l0 * 512.f);
            *(uint16_t*)(rowA + 512 + col) = e4m3x2(v1, v0);
            *(uint16_t*)(rowB + col)       = e4m3x2(l3 * 512.f, l2 * 512.f);
            *(uint16_t*)(rowB + 512 + col) = e4m3x2(v3, v2);
        }
    }
}

// ---------------- launcher ---------------------------------------------------
extern "C" void kernel_launch(void* const* d_in, const int* in_sizes, int n_in,
                              void* d_out, int out_size) {
    (void)in_sizes; (void)n_in; (void)out_size;
    const float* x    = (const float*)d_in[0];
    const float* Wqkv = (const float*)d_in[1];
    const float* Wout = (const float*)d_in[2];
    const float* bout = (const float*)d_in[3];
    float* out = (float*)d_out;

    float* qkv_ptr = nullptr;
    cudaGetSymbolAddress((void**)&qkv_ptr, g_qkv);
    uint8_t *xcat8, *acat8, *wqcat8, *wocat8;
    cudaGetSymbolAddress((void**)&xcat8, g_xcat8);
    cudaGetSymbolAddress((void**)&acat8, g_acat8);
    cudaGetSymbolAddress((void**)&wqcat8, g_wqcat8);
    cudaGetSymbolAddress((void**)&wocat8, g_wocat8);

    cudaFuncSetAttribute(attn_flash_kernel,
                         cudaFuncAttributeMaxDynamicSharedMemorySize,
                         AFL_SMEM);

    rope_table_kernel<<<(TSEQ * 32 + 255) / 256, 256>>>();

    split_cat_kernel<0><<<(MTOT * 128 + 255) / 256, 256>>>(x, xcat8, MTOT * 128);
    split_cat_kernel<1><<<(EQKV * 128 + 255) / 256, 256>>>(Wqkv, wqcat8, EQKV * 128);
    split_cat_kernel<1><<<(DM * 128 + 255) / 256, 256>>>(Wout, wocat8, DM * 128);

    // qkv = x @ Wqkv^T  (bf16 main + fp8 corrections)
    gemm_mma<false><<<dim3(EQKV / 128, MTOT / 128), 256>>>(
        xcat8, wqcat8, nullptr, qkv_ptr, EQKV);

    rope_qk_kernel<<<(NB * TSEQ * NH * 32 + 255) / 256, 256>>>();
    vtrans_kernel<<<dim3(TSEQ / 32, NB * NH), 256>>>();

    // attention writes GEMM2 operand format directly
    attn_flash_kernel<<<dim3(TSEQ / QT, NB * NH), 256, AFL_SMEM>>>();

    // out = attn @ Wout^T + bout
    gemm_mma<true><<<dim3(DM / 128, MTOT / 128), 256>>>(
        acat8, wocat8, bout, out, DM);
}

// round 12
// speedup vs baseline: 1.4802x; 1.4802x over previous
#include <cuda_runtime.h>
#include <cuda_bf16.h>
#include <math.h>
#include <stdint.h>

#define NB 8
#define TSEQ 2048
#define DM 512
#define NH 8
#define HD 64
#define MTOT (NB * TSEQ)          // 16384
#define EQKV (3 * DM)             // 1536
#define GKK 1536                  // concatenated K = 3 * 512

#define QT 64

// ---- flash attention smem layout (bytes) ----
#define AQ_OFF   0                         // 64 x 200 bf16 (Qcat), pitch 400B
#define AK_OFF(s) (25600 + (s) * 43008)    // 64 x 200 bf16 K tile, pitch 400B
#define AV_OFF(s) (AK_OFF(s) + 25600)      // 64 x 136 bf16 V tile (hi|lo), pitch 272B
#define AM_OFF    111616                   // 2 x 64 fp32 (per-half running max)
#define ASUM_OFF  112128                   // 2 x 64 fp32
#define AO_OFF    25600                    // 64 x 64 fp32 exchange (overlays stage0 K)
#define AFL_SMEM  112640

// ---------------- scratch (device globals) ----------------------------------
__device__ float g_qkv[(size_t)MTOT * EQKV];
__device__ float g_cos[TSEQ * 32];
__device__ float g_sin[TSEQ * 32];
__device__ __nv_bfloat16 g_Qc[(size_t)NB * NH * TSEQ * 192];  // [Qh|Ql|Qh]
__device__ __nv_bfloat16 g_Kc[(size_t)NB * NH * TSEQ * 192];  // [Kh|Kh|Kl]
__device__ __nv_bfloat16 g_Vth[(size_t)NB * NH * HD * TSEQ];  // V^T hi [d][t]
__device__ __nv_bfloat16 g_Vtl[(size_t)NB * NH * HD * TSEQ];  // V^T lo [d][t]
__device__ __nv_bfloat16 g_xcat[(size_t)MTOT * GKK];
__device__ __nv_bfloat16 g_acat[(size_t)MTOT * GKK];          // attention out (split)
__device__ __nv_bfloat16 g_wqcat[(size_t)EQKV * GKK];
__device__ __nv_bfloat16 g_wocat[(size_t)DM * GKK];

// ---------------- helpers ----------------------------------------------------
__device__ __forceinline__ uint32_t smem_u32(const void* p) {
    uint32_t a;
    asm("{ .reg .u64 t; cvta.to.shared.u64 t, %1; cvt.u32.u64 %0, t; }"
        : "=r"(a) : "l"(p));
    return a;
}

__device__ __forceinline__ void cp16(uint32_t dst, const void* src) {
    asm volatile("cp.async.cg.shared.global [%0], [%1], 16;"
                 :: "r"(dst), "l"(src) : "memory");
}

__device__ __forceinline__ void ldsm4(uint32_t& r0, uint32_t& r1,
                                      uint32_t& r2, uint32_t& r3, uint32_t addr) {
    asm volatile("ldmatrix.sync.aligned.m8n8.x4.shared.b16 {%0,%1,%2,%3}, [%4];"
                 : "=r"(r0), "=r"(r1), "=r"(r2), "=r"(r3) : "r"(addr));
}

__device__ __forceinline__ void mma16816(float* c, const uint32_t* a,
                                         uint32_t b0, uint32_t b1) {
    asm volatile(
        "mma.sync.aligned.m16n8k16.row.col.f32.bf16.bf16.f32 "
        "{%0,%1,%2,%3}, {%4,%5,%6,%7}, {%8,%9}, {%0,%1,%2,%3};"
        : "+f"(c[0]), "+f"(c[1]), "+f"(c[2]), "+f"(c[3])
        : "r"(a[0]), "r"(a[1]), "r"(a[2]), "r"(a[3]), "r"(b0), "r"(b1));
}

__device__ __forceinline__ void split1(float x, __nv_bfloat16& h, __nv_bfloat16& l) {
    h = __float2bfloat16(x);
    l = __float2bfloat16(x - __bfloat162float(h));
}

__device__ __forceinline__ uint16_t bfbits(__nv_bfloat16 b) {
    return *reinterpret_cast<uint16_t*>(&b);
}

__device__ __forceinline__ uint32_t pack2(float a, float b) {
    __nv_bfloat16 ha = __float2bfloat16(a), hb = __float2bfloat16(b);
    return (uint32_t)bfbits(ha) | ((uint32_t)bfbits(hb) << 16);
}

// pack the bf16 lo-residuals of a,b
__device__ __forceinline__ uint32_t pack2lo(float a, float b) {
    __nv_bfloat16 ha = __float2bfloat16(a), hb = __float2bfloat16(b);
    __nv_bfloat16 la = __float2bfloat16(a - __bfloat162float(ha));
    __nv_bfloat16 lb = __float2bfloat16(b - __bfloat162float(hb));
    return (uint32_t)bfbits(la) | ((uint32_t)bfbits(lb) << 16);
}

// ---------------- bf16 mma.sync GEMM (3-stage pipeline, occ 2) --------------
#define SROW 40
#define STAGE_BYTES (128 * SROW * 2)   // 10240

template <bool BIAS>
__global__ __launch_bounds__(256, 2)
void gemm_mma(const __nv_bfloat16* __restrict__ A, const __nv_bfloat16* __restrict__ B,
              const float* __restrict__ bias, float* __restrict__ C, int N) {
    __shared__ __nv_bfloat16 sA[3][128 * SROW];
    __shared__ __nv_bfloat16 sB[3][128 * SROW];

    const int tid = threadIdx.x;
    const int lid = tid & 31;
    const int wid = tid >> 5;
    const int wm = wid >> 2;
    const int wn = wid & 3;
    const int m0 = blockIdx.y * 128;
    const int n0 = blockIdx.x * 128;
    const uint32_t sAb = smem_u32(sA);
    const uint32_t sBb = smem_u32(sB);

    float acc[4][4][4];
#pragma unroll
    for (int i = 0; i < 4; i++)
#pragma unroll
        for (int j = 0; j < 4; j++)
#pragma unroll
            for (int q = 0; q < 4; q++) acc[i][j][q] = 0.f;

#define PREFETCH(stage, k0)                                                     \
    {                                                                           \
        _Pragma("unroll")                                                       \
        for (int i = 0; i < 2; ++i) {                                           \
            int u = tid + i * 256;                                              \
            int row = u >> 2, c = u & 3;                                        \
            cp16(sAb + (stage) * STAGE_BYTES + row * 80 + c * 16,               \
                 A + (size_t)(m0 + row) * GKK + (k0) + c * 8);                  \
            cp16(sBb + (stage) * STAGE_BYTES + row * 80 + c * 16,               \
                 B + (size_t)(n0 + row) * GKK + (k0) + c * 8);                  \
        }                                                                       \
        asm volatile("cp.async.commit_group;" ::: "memory");                    \
    }

    const int NKT = GKK / 32;   // 48
    PREFETCH(0, 0);
    PREFETCH(1, 32);

    int stage = 0;
    for (int kt = 0; kt < NKT; ++kt) {
        if (kt + 2 < NKT) {
            int ps = stage + 2; if (ps >= 3) ps -= 3;
            PREFETCH(ps, (kt + 2) * 32);
            asm volatile("cp.async.wait_group 2;" ::: "memory");
        } else if (kt + 1 < NKT) {
            asm volatile("cp.async.wait_group 1;" ::: "memory");
        } else {
            asm volatile("cp.async.wait_group 0;" ::: "memory");
        }
        __syncthreads();

        const uint32_t sa = sAb + stage * STAGE_BYTES;
        const uint32_t sb = sBb + stage * STAGE_BYTES;

#pragma unroll
        for (int ks = 0; ks < 32; ks += 16) {
            uint32_t a[4][4], b[2][4];
#pragma unroll
            for (int mi = 0; mi < 4; ++mi) {
                int row = wm * 64 + mi * 16 + (lid & 7) + ((lid >> 3) & 1) * 8;
                int ke = ks + ((lid >> 4) << 3);
                ldsm4(a[mi][0], a[mi][1], a[mi][2], a[mi][3],
                      sa + (uint32_t)(row * SROW + ke) * 2);
            }
#pragma unroll
            for (int nb = 0; nb < 2; ++nb) {
                int n = wn * 32 + nb * 16 + (lid & 7) + ((lid >> 4) & 1) * 8;
                int ke = ks + (((lid >> 3) & 1) << 3);
                ldsm4(b[nb][0], b[nb][1], b[nb][2], b[nb][3],
                      sb + (uint32_t)(n * SROW + ke) * 2);
            }
#pragma unroll
            for (int mi = 0; mi < 4; ++mi)
#pragma unroll
                for (int nf = 0; nf < 4; ++nf)
                    mma16816(acc[mi][nf], a[mi],
                             b[nf >> 1][(nf & 1) * 2], b[nf >> 1][(nf & 1) * 2 + 1]);
        }
        __syncthreads();
        ++stage; if (stage == 3) stage = 0;
    }

    const int r = lid >> 2;
    const int cc = (lid & 3) * 2;
#pragma unroll
    for (int mi = 0; mi < 4; ++mi) {
#pragma unroll
        for (int nf = 0; nf < 4; ++nf) {
            int row = m0 + wm * 64 + mi * 16 + r;
            int col = n0 + wn * 32 + nf * 8 + cc;
            float bx = 0.f, by = 0.f;
            if (BIAS) { bx = bias[col]; by = bias[col + 1]; }
            float2 v0 = make_float2(acc[mi][nf][0] + bx, acc[mi][nf][1] + by);
            float2 v1 = make_float2(acc[mi][nf][2] + bx, acc[mi][nf][3] + by);
            *(float2*)(C + (size_t)row * N + col) = v0;
            *(float2*)(C + (size_t)(row + 8) * N + col) = v1;
        }
    }
#undef PREFETCH
}

// ---------------- fp32 -> concat split (GEMM operands) ----------------------
template <int MODE>
__global__ void split_cat_kernel(const float* __restrict__ src,
                                 __nv_bfloat16* __restrict__ dst, int total4) {
    int i = blockIdx.x * blockDim.x + threadIdx.x;
    if (i >= total4) return;
    int row = i >> 7;
    int c4 = i & 127;
    float4 v = ((const float4*)src)[i];
    __nv_bfloat16 h[4], l[4];
    split1(v.x, h[0], l[0]);
    split1(v.y, h[1], l[1]);
    split1(v.z, h[2], l[2]);
    split1(v.w, h[3], l[3]);
    __nv_bfloat16* d = dst + (size_t)row * GKK + c4 * 4;
    if (MODE == 0) {
        *(uint64_t*)(d)        = *(uint64_t*)h;
        *(uint64_t*)(d + 512)  = *(uint64_t*)l;
        *(uint64_t*)(d + 1024) = *(uint64_t*)h;
    } else {
        *(uint64_t*)(d)        = *(uint64_t*)h;
        *(uint64_t*)(d + 512)  = *(uint64_t*)h;
        *(uint64_t*)(d + 1024) = *(uint64_t*)l;
    }
}

// ---------------- RoPE table ------------------------------------------------
__global__ void rope_table_kernel() {
    int idx = blockIdx.x * blockDim.x + threadIdx.x;
    if (idx >= TSEQ * 32) return;
    int t = idx >> 5;
    int j = idx & 31;
    double inv = exp(-log(10000.0) * (double)j / 32.0);
    float ang = (float)t * (float)inv;
    g_cos[idx] = (float)cos((double)ang);
    g_sin[idx] = (float)sin((double)ang);
}

// ---------------- fused RoPE(Q,K) + V transpose/split -----------------------
// block = (t-block of 32, nh). 256 threads.
__global__ void prep_kernel() {
    __shared__ __nv_bfloat16 svh[64 * 33];
    __shared__ __nv_bfloat16 svl[64 * 33];
    const int tid = threadIdx.x;
    const int nh = blockIdx.y;
    const int n = nh >> 3, h = nh & 7;
    const int t0 = blockIdx.x * 32;

    // ---- RoPE Q/K: 32 t x 32 j pairs = 1024 items ----
#pragma unroll
    for (int it = 0; it < 4; ++it) {
        int e = tid + it * 256;
        int t = t0 + (e >> 5);
        int j = e & 31;

        const float* base = g_qkv + (size_t)(n * TSEQ + t) * EQKV;
        float c = g_cos[t * 32 + j];
        float s = g_sin[t * 32 + j];

        float q1 = base[h * HD + j];
        float q2 = base[h * HD + j + 32];
        float k1 = base[DM + h * HD + j];
        float k2 = base[DM + h * HD + j + 32];

        float q1r = q1 * c - q2 * s;
        float q2r = q2 * c + q1 * s;
        float k1r = k1 * c - k2 * s;
        float k2r = k2 * c + k1 * s;

        __nv_bfloat16 h1, l1, h2, l2;
        __nv_bfloat16* qrow = g_Qc + ((size_t)nh * TSEQ + t) * 192;
        split1(q1r, h1, l1); split1(q2r, h2, l2);
        qrow[j]      = h1; qrow[64 + j] = l1; qrow[128 + j] = h1;
        qrow[32 + j] = h2; qrow[96 + j] = l2; qrow[160 + j] = h2;

        __nv_bfloat16* krow = g_Kc + ((size_t)nh * TSEQ + t) * 192;
        split1(k1r, h1, l1); split1(k2r, h2, l2);
        krow[j]      = h1; krow[64 + j] = h1; krow[128 + j] = l1;
        krow[32 + j] = h2; krow[96 + j] = h2; krow[160 + j] = l2;
    }

    // ---- V transpose + split ----
#pragma unroll
    for (int i = 0; i < 8; i++) {
        int e = tid + i * 256;
        int tl = e >> 6, d = e & 63;
        float v = g_qkv[(size_t)(n * TSEQ + t0 + tl) * EQKV + 2 * DM + h * HD + d];
        __nv_bfloat16 hb, lb;
        split1(v, hb, lb);
        svh[d * 33 + tl] = hb;
        svl[d * 33 + tl] = lb;
    }
    __syncthreads();
#pragma unroll
    for (int i = 0; i < 8; i++) {
        int e = tid + i * 256;
        int d = e >> 5, tl = e & 31;
        size_t o = ((size_t)nh * HD + d) * TSEQ + t0 + tl;
        g_Vth[o] = svh[d * 33 + tl];
        g_Vtl[o] = svl[d * 33 + tl];
    }
}

// ---------------- flash-style banded attention ------------------------------
// CTA per (n*NH+h, 64-q tile). 8 warps: wr = row slice (4), wc = j-half (2).
// Each j-half keeps an independent online softmax; halves merged at the end.
__global__ __launch_bounds__(256, 2)
void attn_flash_kernel() {
    extern __shared__ char smc[];
    const uint32_t sb = smem_u32(smc);
    float* sM   = (float*)(smc + AM_OFF);       // [2][64] per-half running max
    float* sSum = (float*)(smc + ASUM_OFF);     // [2][64]
    float* sO   = (float*)(smc + AO_OFF);       // [64][64]

    const int tid = threadIdx.x;
    const int lid = tid & 31, wid = tid >> 5;
    const int wr = wid & 3, wc = wid >> 2;
    const int q0 = blockIdx.x * QT;
    const int nh = blockIdx.y;
    const int n = nh >> 3, h = nh & 7;
    const int ks = q0 - 128;
    const float scale = 0.125f;

    const int rlo = wr * 16 + (lid >> 2);
    const int rhi = rlo + 8;

    // ---- Q tile ----
#pragma unroll
    for (int i = 0; i < 6; i++) {
        int u = tid + i * 256;
        int r = u / 24, c = u % 24;
        cp16(sb + AQ_OFF + r * 400 + c * 16,
             g_Qc + ((size_t)nh * TSEQ + q0 + r) * 192 + c * 8);
    }

#define ISSUE_KV(jt_, st_)                                                      \
    {                                                                           \
        _Pragma("unroll")                                                       \
        for (int i = 0; i < 6; i++) {                                           \
            int u = tid + i * 256;                                              \
            int r = u / 24, c = u % 24;                                         \
            int j = ks + (jt_) * 64 + r;                                        \
            j = j < 0 ? 0 : (j > TSEQ - 1 ? TSEQ - 1 : j);                      \
            cp16(sb + AK_OFF(st_) + r * 400 + c * 16,                           \
                 g_Kc + ((size_t)nh * TSEQ + j) * 192 + c * 8);                 \
        }                                                                       \
        _Pragma("unroll")                                                       \
        for (int i = 0; i < 4; i++) {                                           \
            int u = tid + i * 256;                                              \
            int r = u >> 4, c = u & 15;                                         \
            int jb = ks + (jt_) * 64 + (c & 7) * 8;                             \
            jb = jb < 0 ? 0 : (jb > TSEQ - 8 ? TSEQ - 8 : jb);                  \
            const __nv_bfloat16* vs = (c < 8) ? g_Vth : g_Vtl;                  \
            cp16(sb + AV_OFF(st_) + r * 272 + c * 16,                           \
                 vs + ((size_t)nh * HD + r) * TSEQ + jb);                       \
        }                                                                       \
        asm volatile("cp.async.commit_group;" ::: "memory");                    \
    }

    ISSUE_KV(0, 0);

    float oacc[8][4];
#pragma unroll
    for (int i = 0; i < 8; i++)
#pragma unroll
        for (int q = 0; q < 4; q++) oacc[i][q] = 0.f;
    float m0 = -1e30f, m1 = -1e30f;          // per-half running max
    float sum0 = 0.f, sum1 = 0.f;

    for (int jt = 0; jt < 5; ++jt) {
        const int st = jt & 1;
        if (jt < 4) {
            ISSUE_KV(jt + 1, st ^ 1);
            asm volatile("cp.async.wait_group 1;" ::: "memory");
        } else {
            asm volatile("cp.async.wait_group 0;" ::: "memory");
        }
        __syncthreads();

        // ---- S = Qcat · Kcat^T (this warp: 16 rows x 32 cols) ----
        float sacc[4][4];
#pragma unroll
        for (int i = 0; i < 4; i++)
#pragma unroll
            for (int q = 0; q < 4; q++) sacc[i][q] = 0.f;

        const uint32_t kb = sb + AK_OFF(st);
#pragma unroll
        for (int k16 = 0; k16 < 12; ++k16) {
            uint32_t a[4], b[2][4];
            {
                int row = wr * 16 + (lid & 7) + ((lid >> 3) & 1) * 8;
                int ke = k16 * 16 + ((lid >> 4) << 3);
                ldsm4(a[0], a[1], a[2], a[3], sb + AQ_OFF + row * 400 + ke * 2);
            }
#pragma unroll
            for (int nb = 0; nb < 2; ++nb) {
                int nn = wc * 32 + nb * 16 + (lid & 7) + ((lid >> 4) & 1) * 8;
                int ke = k16 * 16 + (((lid >> 3) & 1) << 3);
                ldsm4(b[nb][0], b[nb][1], b[nb][2], b[nb][3], kb + nn * 400 + ke * 2);
            }
#pragma unroll
            for (int nf = 0; nf < 4; ++nf)
                mma16816(sacc[nf], a, b[nf >> 1][(nf & 1) * 2],
                         b[nf >> 1][(nf & 1) * 2 + 1]);
        }

        // ---- mask + scale in regs ----
#pragma unroll
        for (int nf = 0; nf < 4; ++nf) {
#pragma unroll
            for (int e = 0; e < 2; ++e) {
                int j = ks + jt * 64 + wc * 32 + nf * 8 + 2 * (lid & 3) + e;
                int d0 = j - (q0 + rlo);
                int d1 = j - (q0 + rhi);
                bool in = (j >= 0) && (j < TSEQ);
                sacc[nf][e]     = (in && d0 >= -127 && d0 <= 128)
                                  ? sacc[nf][e] * scale : -1e30f;
                sacc[nf][2 + e] = (in && d1 >= -127 && d1 <= 128)
                                  ? sacc[nf][2 + e] * scale : -1e30f;
            }
        }

        // ---- per-half online softmax (quad reduction only, no CTA sync) ----
        float mx0 = sacc[0][0], mx1 = sacc[0][2];
#pragma unroll
        for (int nf = 0; nf < 4; ++nf) {
            mx0 = fmaxf(mx0, fmaxf(sacc[nf][0], sacc[nf][1]));
            mx1 = fmaxf(mx1, fmaxf(sacc[nf][2], sacc[nf][3]));
        }
        mx0 = fmaxf(mx0, __shfl_xor_sync(0xffffffffu, mx0, 1));
        mx0 = fmaxf(mx0, __shfl_xor_sync(0xffffffffu, mx0, 2));
        mx1 = fmaxf(mx1, __shfl_xor_sync(0xffffffffu, mx1, 1));
        mx1 = fmaxf(mx1, __shfl_xor_sync(0xffffffffu, mx1, 2));
        float nm0 = fmaxf(m0, mx0);
        float nm1 = fmaxf(m1, mx1);
        float f0 = __expf(m0 - nm0);
        float f1 = __expf(m1 - nm1);
        m0 = nm0; m1 = nm1;
        sum0 *= f0; sum1 *= f1;
#pragma unroll
        for (int i = 0; i < 8; i++) {
            oacc[i][0] *= f0; oacc[i][1] *= f0;
            oacc[i][2] *= f1; oacc[i][3] *= f1;
        }

        // ---- P = exp(S - m); pack to bf16 hi/lo A-frags ----
        uint32_t ph[2][4], pl[2][4];
#pragma unroll
        for (int nf = 0; nf < 4; ++nf) {
            float p0 = __expf(sacc[nf][0] - nm0);
            float p1 = __expf(sacc[nf][1] - nm0);
            float p2 = __expf(sacc[nf][2] - nm1);
            float p3 = __expf(sacc[nf][3] - nm1);
            sum0 += p0 + p1;
            sum1 += p2 + p3;
            int b = nf >> 1;
            int o = (nf & 1) * 2;
            ph[b][o]     = pack2(p0, p1);
            ph[b][o + 1] = pack2(p2, p3);
            pl[b][o]     = pack2lo(p0, p1);
            pl[b][o + 1] = pack2lo(p2, p3);
        }

        // ---- O += Pcat · Vcat (this warp's 32 j-cols; 3-term split) ----
        const uint32_t vb = sb + AV_OFF(st);
#pragma unroll
        for (int b = 0; b < 2; ++b) {
            int kcol = wc * 32 + b * 16;
            uint32_t v[4][4];
#pragma unroll
            for (int dnb = 0; dnb < 4; ++dnb) {
                int nn = dnb * 16 + (lid & 7) + ((lid >> 4) & 1) * 8;
                int kk = kcol + (((lid >> 3) & 1) << 3);
                ldsm4(v[dnb][0], v[dnb][1], v[dnb][2], v[dnb][3],
                      vb + nn * 272 + kk * 2);          // V hi
            }
#pragma unroll
            for (int n8 = 0; n8 < 8; ++n8) {
                mma16816(oacc[n8], ph[b], v[n8 >> 1][(n8 & 1) * 2],
                         v[n8 >> 1][(n8 & 1) * 2 + 1]);
                mma16816(oacc[n8], pl[b], v[n8 >> 1][(n8 & 1) * 2],
                         v[n8 >> 1][(n8 & 1) * 2 + 1]);
            }
#pragma unroll
            for (int dnb = 0; dnb < 4; ++dnb) {
                int nn = dnb * 16 + (lid & 7) + ((lid >> 4) & 1) * 8;
                int kk = kcol + (((lid >> 3) & 1) << 3);
                ldsm4(v[dnb][0], v[dnb][1], v[dnb][2], v[dnb][3],
                      vb + nn * 272 + 128 + kk * 2);    // V lo
            }
#pragma unroll
            for (int n8 = 0; n8 < 8; ++n8)
                mma16816(oacc[n8], ph[b], v[n8 >> 1][(n8 & 1) * 2],
                         v[n8 >> 1][(n8 & 1) * 2 + 1]);
        }
        __syncthreads();   // done reading this stage before its next overwrite
    }
#undef ISSUE_KV

    // ---- merge the two j-halves (split-KV combine), normalize, write ----
    sum0 += __shfl_xor_sync(0xffffffffu, sum0, 1);
    sum0 += __shfl_xor_sync(0xffffffffu, sum0, 2);
    sum1 += __shfl_xor_sync(0xffffffffu, sum1, 1);
    sum1 += __shfl_xor_sync(0xffffffffu, sum1, 2);
    if ((lid & 3) == 0) {
        sSum[wc * 64 + rlo] = sum0;
        sSum[wc * 64 + rhi] = sum1;
        sM[wc * 64 + rlo] = m0;
        sM[wc * 64 + rhi] = m1;
    }
    if (wc == 1) {
#pragma unroll
        for (int i = 0; i < 8; i++) {
            int d = i * 8 + 2 * (lid & 3);
            sO[rlo * 64 + d] = oacc[i][0];
            sO[rlo * 64 + d + 1] = oacc[i][1];
            sO[rhi * 64 + d] = oacc[i][2];
            sO[rhi * 64 + d + 1] = oacc[i][3];
        }
    }
    __syncthreads();
    if (wc == 0) {
        float mo0 = sM[64 + rlo], mo1 = sM[64 + rhi];
        float M0 = fmaxf(m0, mo0), M1 = fmaxf(m1, mo1);
        float fs0 = __expf(m0 - M0), fo0 = __expf(mo0 - M0);
        float fs1 = __expf(m1 - M1), fo1 = __expf(mo1 - M1);
        float inv0 = 1.f / (sSum[rlo] * fs0 + sSum[64 + rlo] * fo0);
        float inv1 = 1.f / (sSum[rhi] * fs1 + sSum[64 + rhi] * fo1);
        __nv_bfloat16* outLo = g_acat + ((size_t)(n * TSEQ) + q0 + rlo) * GKK + h * HD;
        __nv_bfloat16* outHi = g_acat + ((size_t)(n * TSEQ) + q0 + rhi) * GKK + h * HD;
#pragma unroll
        for (int i = 0; i < 8; i++) {
            int d = i * 8 + 2 * (lid & 3);
            float v0 = (oacc[i][0] * fs0 + sO[rlo * 64 + d] * fo0) * inv0;
            float v1 = (oacc[i][1] * fs0 + sO[rlo * 64 + d + 1] * fo0) * inv0;
            float v2 = (oacc[i][2] * fs1 + sO[rhi * 64 + d] * fo1) * inv1;
            float v3 = (oacc[i][3] * fs1 + sO[rhi * 64 + d + 1] * fo1) * inv1;
            uint32_t h01 = pack2(v0, v1), l01 = pack2lo(v0, v1);
            uint32_t h23 = pack2(v2, v3), l23 = pack2lo(v2, v3);
            *(uint32_t*)(outLo + d)        = h01;
            *(uint32_t*)(outLo + d + 512)  = l01;
            *(uint32_t*)(outLo + d + 1024) = h01;
            *(uint32_t*)(outHi + d)        = h23;
            *(uint32_t*)(outHi + d + 512)  = l23;
            *(uint32_t*)(outHi + d + 1024) = h23;
        }
    }
}

// ---------------- launcher ---------------------------------------------------
extern "C" void kernel_launch(void* const* d_in, const int* in_sizes, int n_in,
                              void* d_out, int out_size) {
    (void)in_sizes; (void)n_in; (void)out_size;
    const float* x    = (const float*)d_in[0];
    const float* Wqkv = (const float*)d_in[1];
    const float* Wout = (const float*)d_in[2];
    const float* bout = (const float*)d_in[3];
    float* out = (float*)d_out;

    float* qkv_ptr = nullptr;
    cudaGetSymbolAddress((void**)&qkv_ptr, g_qkv);
    __nv_bfloat16 *xcat, *acat, *wqcat, *wocat;
    cudaGetSymbolAddress((void**)&xcat, g_xcat);
    cudaGetSymbolAddress((void**)&acat, g_acat);
    cudaGetSymbolAddress((void**)&wqcat, g_wqcat);
    cudaGetSymbolAddress((void**)&wocat, g_wocat);

    cudaFuncSetAttribute(attn_flash_kernel,
                         cudaFuncAttributeMaxDynamicSharedMemorySize,
                         AFL_SMEM);

    rope_table_kernel<<<(TSEQ * 32 + 255) / 256, 256>>>();

    split_cat_kernel<0><<<(MTOT * 128 + 255) / 256, 256>>>(x, xcat, MTOT * 128);
    split_cat_kernel<1><<<(EQKV * 128 + 255) / 256, 256>>>(Wqkv, wqcat, EQKV * 128);
    split_cat_kernel<1><<<(DM * 128 + 255) / 256, 256>>>(Wout, wocat, DM * 128);

    // qkv = x @ Wqkv^T  (split-bf16 HMMA, K=1536)
    gemm_mma<false><<<dim3(EQKV / 128, MTOT / 128), 256>>>(
        xcat, wqcat, nullptr, qkv_ptr, EQKV);

    // fused RoPE + V transpose
    prep_kernel<<<dim3(TSEQ / 32, NB * NH), 256>>>();

    // attention writes split-concat output (acat) directly
    attn_flash_kernel<<<dim3(TSEQ / QT, NB * NH), 256, AFL_SMEM>>>();

    // out = attn @ Wout^T + bout
    gemm_mma<true><<<dim3(DM / 128, MTOT / 128), 256>>>(
        acat, wocat, bout, out, DM);
}

// round 13
// speedup vs baseline: 1.7123x; 1.1568x over previous
#include <cuda_runtime.h>
#include <cuda_bf16.h>
#include <math.h>
#include <stdint.h>

#define NB 8
#define TSEQ 2048
#define DM 512
#define NH 8
#define HD 64
#define MTOT (NB * TSEQ)          // 16384
#define EQKV (3 * DM)             // 1536
#define GKD 1024                  // operand row: [hi 512 | lo 512] bf16

#define QT 64

// ---- flash attention smem layout (bytes) ----
#define AQ_OFF   0                         // 64 x 200 bf16 (Qcat), pitch 400B
#define AK_OFF(s) (25600 + (s) * 43008)    // 64 x 200 bf16 K tile, pitch 400B
#define AV_OFF(s) (AK_OFF(s) + 25600)      // 64 x 136 bf16 V tile (hi|lo), pitch 272B
#define AM_OFF    111616                   // 2 x 64 fp32 (per-half running max)
#define ASUM_OFF  112128                   // 2 x 64 fp32
#define AO_OFF    25600                    // 64 x 64 fp32 exchange (overlays stage0 K)
#define AFL_SMEM  112640

// ---------------- scratch (device globals) ----------------------------------
__device__ float g_qkv[(size_t)MTOT * EQKV];
__device__ float g_cos[TSEQ * 32];
__device__ float g_sin[TSEQ * 32];
__device__ __nv_bfloat16 g_Qc[(size_t)NB * NH * TSEQ * 192];  // [Qh|Ql|Qh]
__device__ __nv_bfloat16 g_Kc[(size_t)NB * NH * TSEQ * 192];  // [Kh|Kh|Kl]
__device__ __nv_bfloat16 g_Vth[(size_t)NB * NH * HD * TSEQ];  // V^T hi [d][t]
__device__ __nv_bfloat16 g_Vtl[(size_t)NB * NH * HD * TSEQ];  // V^T lo [d][t]
__device__ __nv_bfloat16 g_xcat[(size_t)MTOT * GKD];          // x [hi|lo]
__device__ __nv_bfloat16 g_acat[(size_t)MTOT * GKD];          // attn out [hi|lo]
__device__ __nv_bfloat16 g_wqcat[(size_t)EQKV * GKD];
__device__ __nv_bfloat16 g_wocat[(size_t)DM * GKD];

// ---------------- helpers ----------------------------------------------------
__device__ __forceinline__ uint32_t smem_u32(const void* p) {
    uint32_t a;
    asm("{ .reg .u64 t; cvta.to.shared.u64 t, %1; cvt.u32.u64 %0, t; }"
        : "=r"(a) : "l"(p));
    return a;
}

__device__ __forceinline__ void cp16(uint32_t dst, const void* src) {
    asm volatile("cp.async.cg.shared.global [%0], [%1], 16;"
                 :: "r"(dst), "l"(src) : "memory");
}

__device__ __forceinline__ void ldsm4(uint32_t& r0, uint32_t& r1,
                                      uint32_t& r2, uint32_t& r3, uint32_t addr) {
    asm volatile("ldmatrix.sync.aligned.m8n8.x4.shared.b16 {%0,%1,%2,%3}, [%4];"
                 : "=r"(r0), "=r"(r1), "=r"(r2), "=r"(r3) : "r"(addr));
}

__device__ __forceinline__ void mma16816(float* c, const uint32_t* a,
                                         uint32_t b0, uint32_t b1) {
    asm volatile(
        "mma.sync.aligned.m16n8k16.row.col.f32.bf16.bf16.f32 "
        "{%0,%1,%2,%3}, {%4,%5,%6,%7}, {%8,%9}, {%0,%1,%2,%3};"
        : "+f"(c[0]), "+f"(c[1]), "+f"(c[2]), "+f"(c[3])
        : "r"(a[0]), "r"(a[1]), "r"(a[2]), "r"(a[3]), "r"(b0), "r"(b1));
}

__device__ __forceinline__ void split1(float x, __nv_bfloat16& h, __nv_bfloat16& l) {
    h = __float2bfloat16(x);
    l = __float2bfloat16(x - __bfloat162float(h));
}

__device__ __forceinline__ uint16_t bfbits(__nv_bfloat16 b) {
    return *reinterpret_cast<uint16_t*>(&b);
}

__device__ __forceinline__ uint32_t pack2(float a, float b) {
    __nv_bfloat16 ha = __float2bfloat16(a), hb = __float2bfloat16(b);
    return (uint32_t)bfbits(ha) | ((uint32_t)bfbits(hb) << 16);
}

// pack the bf16 lo-residuals of a,b
__device__ __forceinline__ uint32_t pack2lo(float a, float b) {
    __nv_bfloat16 ha = __float2bfloat16(a), hb = __float2bfloat16(b);
    __nv_bfloat16 la = __float2bfloat16(a - __bfloat162float(ha));
    __nv_bfloat16 lb = __float2bfloat16(b - __bfloat162float(hb));
    return (uint32_t)bfbits(la) | ((uint32_t)bfbits(lb) << 16);
}

// ---------------- split-bf16 GEMM, de-duplicated operands -------------------
// C = Ah·Bh^T + Ah·Bl^T + Al·Bh^T, operands stored [hi|lo] per row.
// Per 32-K chunk: load 4 tiles (AH,AL,BH,BL), 3 register-level term passes.
#define SROW 40
#define TILE_B (128 * SROW * 2)     // 10240 bytes per tile
#define STG (4 * TILE_B)            // 40960 bytes per stage

template <bool BIAS>
__global__ __launch_bounds__(256, 2)
void gemm_mma(const __nv_bfloat16* __restrict__ A, const __nv_bfloat16* __restrict__ B,
              const float* __restrict__ bias, float* __restrict__ C, int N) {
    __shared__ __nv_bfloat16 smem_t[2][4][128 * SROW];   // [stage][AH,AL,BH,BL]

    const int tid = threadIdx.x;
    const int lid = tid & 31;
    const int wid = tid >> 5;
    const int wm = wid >> 2;
    const int wn = wid & 3;
    const int m0 = blockIdx.y * 128;
    const int n0 = blockIdx.x * 128;
    const uint32_t smb = smem_u32(smem_t);

    float acc[4][4][4];
#pragma unroll
    for (int i = 0; i < 4; i++)
#pragma unroll
        for (int j = 0; j < 4; j++)
#pragma unroll
            for (int q = 0; q < 4; q++) acc[i][j][q] = 0.f;

    // 2048 cp16 per stage (4 tiles x 512), 8 per thread
#define PREFETCH(st_, kt_)                                                      \
    {                                                                           \
        _Pragma("unroll")                                                       \
        for (int i = 0; i < 8; ++i) {                                           \
            int u = tid + i * 256;                                              \
            int tile = u >> 9;                                                  \
            int v = u & 511;                                                    \
            int row = v >> 2, c = v & 3;                                        \
            const __nv_bfloat16* src =                                          \
                (tile < 2 ? A + (size_t)(m0 + row) * GKD                        \
                          : B + (size_t)(n0 + row) * GKD)                       \
                + (tile & 1) * 512 + (kt_) * 32 + c * 8;                        \
            cp16(smb + (st_) * STG + tile * TILE_B + row * 80 + c * 16, src);   \
        }                                                                       \
        asm volatile("cp.async.commit_group;" ::: "memory");                    \
    }

    const int NKT = 16;     // 16 chunks of 32 over the distinct K=512
    PREFETCH(0, 0);

    for (int kt = 0; kt < NKT; ++kt) {
        const int st = kt & 1;
        if (kt + 1 < NKT) {
            PREFETCH(st ^ 1, kt + 1);
            asm volatile("cp.async.wait_group 1;" ::: "memory");
        } else {
            asm volatile("cp.async.wait_group 0;" ::: "memory");
        }
        __syncthreads();

        const uint32_t sAH = smb + st * STG;
        const uint32_t sAL = sAH + TILE_B;
        const uint32_t sBH = sAL + TILE_B;
        const uint32_t sBL = sBH + TILE_B;

#pragma unroll
        for (int ks = 0; ks < 32; ks += 16) {
            uint32_t a[4][4], bh[2][4], bl[2][4];
#pragma unroll
            for (int nb = 0; nb < 2; ++nb) {
                int n = wn * 32 + nb * 16 + (lid & 7) + ((lid >> 4) & 1) * 8;
                int ke = ks + (((lid >> 3) & 1) << 3);
                ldsm4(bh[nb][0], bh[nb][1], bh[nb][2], bh[nb][3],
                      sBH + (uint32_t)(n * SROW + ke) * 2);
                ldsm4(bl[nb][0], bl[nb][1], bl[nb][2], bl[nb][3],
                      sBL + (uint32_t)(n * SROW + ke) * 2);
            }
            // Ah pass: vs Bh and Bl
#pragma unroll
            for (int mi = 0; mi < 4; ++mi) {
                int row = wm * 64 + mi * 16 + (lid & 7) + ((lid >> 3) & 1) * 8;
                int ke = ks + ((lid >> 4) << 3);
                ldsm4(a[mi][0], a[mi][1], a[mi][2], a[mi][3],
                      sAH + (uint32_t)(row * SROW + ke) * 2);
            }
#pragma unroll
            for (int mi = 0; mi < 4; ++mi)
#pragma unroll
                for (int nf = 0; nf < 4; ++nf) {
                    mma16816(acc[mi][nf], a[mi],
                             bh[nf >> 1][(nf & 1) * 2], bh[nf >> 1][(nf & 1) * 2 + 1]);
                    mma16816(acc[mi][nf], a[mi],
                             bl[nf >> 1][(nf & 1) * 2], bl[nf >> 1][(nf & 1) * 2 + 1]);
                }
            // Al pass: vs Bh only
#pragma unroll
            for (int mi = 0; mi < 4; ++mi) {
                int row = wm * 64 + mi * 16 + (lid & 7) + ((lid >> 3) & 1) * 8;
                int ke = ks + ((lid >> 4) << 3);
                ldsm4(a[mi][0], a[mi][1], a[mi][2], a[mi][3],
                      sAL + (uint32_t)(row * SROW + ke) * 2);
            }
#pragma unroll
            for (int mi = 0; mi < 4; ++mi)
#pragma unroll
                for (int nf = 0; nf < 4; ++nf)
                    mma16816(acc[mi][nf], a[mi],
                             bh[nf >> 1][(nf & 1) * 2], bh[nf >> 1][(nf & 1) * 2 + 1]);
        }
        __syncthreads();
    }

    const int r = lid >> 2;
    const int cc = (lid & 3) * 2;
#pragma unroll
    for (int mi = 0; mi < 4; ++mi) {
#pragma unroll
        for (int nf = 0; nf < 4; ++nf) {
            int row = m0 + wm * 64 + mi * 16 + r;
            int col = n0 + wn * 32 + nf * 8 + cc;
            float bx = 0.f, by = 0.f;
            if (BIAS) { bx = bias[col]; by = bias[col + 1]; }
            float2 v0 = make_float2(acc[mi][nf][0] + bx, acc[mi][nf][1] + by);
            float2 v1 = make_float2(acc[mi][nf][2] + bx, acc[mi][nf][3] + by);
            *(float2*)(C + (size_t)row * N + col) = v0;
            *(float2*)(C + (size_t)(row + 8) * N + col) = v1;
        }
    }
#undef PREFETCH
}

// ---------------- fp32 -> [hi|lo] split -------------------------------------
__global__ void split_kernel(const float* __restrict__ src,
                             __nv_bfloat16* __restrict__ dst, int total4) {
    int i = blockIdx.x * blockDim.x + threadIdx.x;
    if (i >= total4) return;
    int row = i >> 7;          // 128 float4 per 512-float row
    int c4 = i & 127;
    float4 v = ((const float4*)src)[i];
    __nv_bfloat16 h[4], l[4];
    split1(v.x, h[0], l[0]);
    split1(v.y, h[1], l[1]);
    split1(v.z, h[2], l[2]);
    split1(v.w, h[3], l[3]);
    __nv_bfloat16* d = dst + (size_t)row * GKD + c4 * 4;
    *(uint64_t*)(d)       = *(uint64_t*)h;
    *(uint64_t*)(d + 512) = *(uint64_t*)l;
}

// ---------------- RoPE table ------------------------------------------------
__global__ void rope_table_kernel() {
    int idx = blockIdx.x * blockDim.x + threadIdx.x;
    if (idx >= TSEQ * 32) return;
    int t = idx >> 5;
    int j = idx & 31;
    double inv = exp(-log(10000.0) * (double)j / 32.0);
    float ang = (float)t * (float)inv;
    g_cos[idx] = (float)cos((double)ang);
    g_sin[idx] = (float)sin((double)ang);
}

// ---------------- fused RoPE(Q,K) + V transpose/split -----------------------
__global__ void prep_kernel() {
    __shared__ __nv_bfloat16 svh[64 * 33];
    __shared__ __nv_bfloat16 svl[64 * 33];
    const int tid = threadIdx.x;
    const int nh = blockIdx.y;
    const int n = nh >> 3, h = nh & 7;
    const int t0 = blockIdx.x * 32;

#pragma unroll
    for (int it = 0; it < 4; ++it) {
        int e = tid + it * 256;
        int t = t0 + (e >> 5);
        int j = e & 31;

        const float* base = g_qkv + (size_t)(n * TSEQ + t) * EQKV;
        float c = g_cos[t * 32 + j];
        float s = g_sin[t * 32 + j];

        float q1 = base[h * HD + j];
        float q2 = base[h * HD + j + 32];
        float k1 = base[DM + h * HD + j];
        float k2 = base[DM + h * HD + j + 32];

        float q1r = q1 * c - q2 * s;
        float q2r = q2 * c + q1 * s;
        float k1r = k1 * c - k2 * s;
        float k2r = k2 * c + k1 * s;

        __nv_bfloat16 h1, l1, h2, l2;
        __nv_bfloat16* qrow = g_Qc + ((size_t)nh * TSEQ + t) * 192;
        split1(q1r, h1, l1); split1(q2r, h2, l2);
        qrow[j]      = h1; qrow[64 + j] = l1; qrow[128 + j] = h1;
        qrow[32 + j] = h2; qrow[96 + j] = l2; qrow[160 + j] = h2;

        __nv_bfloat16* krow = g_Kc + ((size_t)nh * TSEQ + t) * 192;
        split1(k1r, h1, l1); split1(k2r, h2, l2);
        krow[j]      = h1; krow[64 + j] = h1; krow[128 + j] = l1;
        krow[32 + j] = h2; krow[96 + j] = h2; krow[160 + j] = l2;
    }

#pragma unroll
    for (int i = 0; i < 8; i++) {
        int e = tid + i * 256;
        int tl = e >> 6, d = e & 63;
        float v = g_qkv[(size_t)(n * TSEQ + t0 + tl) * EQKV + 2 * DM + h * HD + d];
        __nv_bfloat16 hb, lb;
        split1(v, hb, lb);
        svh[d * 33 + tl] = hb;
        svl[d * 33 + tl] = lb;
    }
    __syncthreads();
#pragma unroll
    for (int i = 0; i < 8; i++) {
        int e = tid + i * 256;
        int d = e >> 5, tl = e & 31;
        size_t o = ((size_t)nh * HD + d) * TSEQ + t0 + tl;
        g_Vth[o] = svh[d * 33 + tl];
        g_Vtl[o] = svl[d * 33 + tl];
    }
}

// ---------------- flash-style banded attention ------------------------------
__global__ __launch_bounds__(256, 2)
void attn_flash_kernel() {
    extern __shared__ char smc[];
    const uint32_t sb = smem_u32(smc);
    float* sM   = (float*)(smc + AM_OFF);       // [2][64]
    float* sSum = (float*)(smc + ASUM_OFF);     // [2][64]
    float* sO   = (float*)(smc + AO_OFF);       // [64][64]

    const int tid = threadIdx.x;
    const int lid = tid & 31, wid = tid >> 5;
    const int wr = wid & 3, wc = wid >> 2;
    const int q0 = blockIdx.x * QT;
    const int nh = blockIdx.y;
    const int n = nh >> 3, h = nh & 7;
    const int ks = q0 - 128;
    const float scale = 0.125f;

    const int rlo = wr * 16 + (lid >> 2);
    const int rhi = rlo + 8;

    // ---- Q tile ----
#pragma unroll
    for (int i = 0; i < 6; i++) {
        int u = tid + i * 256;
        int r = u / 24, c = u % 24;
        cp16(sb + AQ_OFF + r * 400 + c * 16,
             g_Qc + ((size_t)nh * TSEQ + q0 + r) * 192 + c * 8);
    }

#define ISSUE_KV(jt_, st_)                                                      \
    {                                                                           \
        _Pragma("unroll")                                                       \
        for (int i = 0; i < 6; i++) {                                           \
            int u = tid + i * 256;                                              \
            int r = u / 24, c = u % 24;                                         \
            int j = ks + (jt_) * 64 + r;                                        \
            j = j < 0 ? 0 : (j > TSEQ - 1 ? TSEQ - 1 : j);                      \
            cp16(sb + AK_OFF(st_) + r * 400 + c * 16,                           \
                 g_Kc + ((size_t)nh * TSEQ + j) * 192 + c * 8);                 \
        }                                                                       \
        _Pragma("unroll")                                                       \
        for (int i = 0; i < 4; i++) {                                           \
            int u = tid + i * 256;                                              \
            int r = u >> 4, c = u & 15;                                         \
            int jb = ks + (jt_) * 64 + (c & 7) * 8;                             \
            jb = jb < 0 ? 0 : (jb > TSEQ - 8 ? TSEQ - 8 : jb);                  \
            const __nv_bfloat16* vs = (c < 8) ? g_Vth : g_Vtl;                  \
            cp16(sb + AV_OFF(st_) + r * 272 + c * 16,                           \
                 vs + ((size_t)nh * HD + r) * TSEQ + jb);                       \
        }                                                                       \
        asm volatile("cp.async.commit_group;" ::: "memory");                    \
    }

    ISSUE_KV(0, 0);

    float oacc[8][4];
#pragma unroll
    for (int i = 0; i < 8; i++)
#pragma unroll
        for (int q = 0; q < 4; q++) oacc[i][q] = 0.f;
    float m0 = -1e30f, m1 = -1e30f;
    float sum0 = 0.f, sum1 = 0.f;

    for (int jt = 0; jt < 5; ++jt) {
        const int st = jt & 1;
        if (jt < 4) {
            ISSUE_KV(jt + 1, st ^ 1);
            asm volatile("cp.async.wait_group 1;" ::: "memory");
        } else {
            asm volatile("cp.async.wait_group 0;" ::: "memory");
        }
        __syncthreads();

        float sacc[4][4];
#pragma unroll
        for (int i = 0; i < 4; i++)
#pragma unroll
            for (int q = 0; q < 4; q++) sacc[i][q] = 0.f;

        const uint32_t kb = sb + AK_OFF(st);
#pragma unroll
        for (int k16 = 0; k16 < 12; ++k16) {
            uint32_t a[4], b[2][4];
            {
                int row = wr * 16 + (lid & 7) + ((lid >> 3) & 1) * 8;
                int ke = k16 * 16 + ((lid >> 4) << 3);
                ldsm4(a[0], a[1], a[2], a[3], sb + AQ_OFF + row * 400 + ke * 2);
            }
#pragma unroll
            for (int nb = 0; nb < 2; ++nb) {
                int nn = wc * 32 + nb * 16 + (lid & 7) + ((lid >> 4) & 1) * 8;
                int ke = k16 * 16 + (((lid >> 3) & 1) << 3);
                ldsm4(b[nb][0], b[nb][1], b[nb][2], b[nb][3], kb + nn * 400 + ke * 2);
            }
#pragma unroll
            for (int nf = 0; nf < 4; ++nf)
                mma16816(sacc[nf], a, b[nf >> 1][(nf & 1) * 2],
                         b[nf >> 1][(nf & 1) * 2 + 1]);
        }

#pragma unroll
        for (int nf = 0; nf < 4; ++nf) {
#pragma unroll
            for (int e = 0; e < 2; ++e) {
                int j = ks + jt * 64 + wc * 32 + nf * 8 + 2 * (lid & 3) + e;
                int d0 = j - (q0 + rlo);
                int d1 = j - (q0 + rhi);
                bool in = (j >= 0) && (j < TSEQ);
                sacc[nf][e]     = (in && d0 >= -127 && d0 <= 128)
                                  ? sacc[nf][e] * scale : -1e30f;
                sacc[nf][2 + e] = (in && d1 >= -127 && d1 <= 128)
                                  ? sacc[nf][2 + e] * scale : -1e30f;
            }
        }

        float mx0 = sacc[0][0], mx1 = sacc[0][2];
#pragma unroll
        for (int nf = 0; nf < 4; ++nf) {
            mx0 = fmaxf(mx0, fmaxf(sacc[nf][0], sacc[nf][1]));
            mx1 = fmaxf(mx1, fmaxf(sacc[nf][2], sacc[nf][3]));
        }
        mx0 = fmaxf(mx0, __shfl_xor_sync(0xffffffffu, mx0, 1));
        mx0 = fmaxf(mx0, __shfl_xor_sync(0xffffffffu, mx0, 2));
        mx1 = fmaxf(mx1, __shfl_xor_sync(0xffffffffu, mx1, 1));
        mx1 = fmaxf(mx1, __shfl_xor_sync(0xffffffffu, mx1, 2));
        float nm0 = fmaxf(m0, mx0);
        float nm1 = fmaxf(m1, mx1);
        float f0 = __expf(m0 - nm0);
        float f1 = __expf(m1 - nm1);
        m0 = nm0; m1 = nm1;
        sum0 *= f0; sum1 *= f1;
#pragma unroll
        for (int i = 0; i < 8; i++) {
            oacc[i][0] *= f0; oacc[i][1] *= f0;
            oacc[i][2] *= f1; oacc[i][3] *= f1;
        }

        uint32_t ph[2][4], pl[2][4];
#pragma unroll
        for (int nf = 0; nf < 4; ++nf) {
            float p0 = __expf(sacc[nf][0] - nm0);
            float p1 = __expf(sacc[nf][1] - nm0);
            float p2 = __expf(sacc[nf][2] - nm1);
            float p3 = __expf(sacc[nf][3] - nm1);
            sum0 += p0 + p1;
            sum1 += p2 + p3;
            int b = nf >> 1;
            int o = (nf & 1) * 2;
            ph[b][o]     = pack2(p0, p1);
            ph[b][o + 1] = pack2(p2, p3);
            pl[b][o]     = pack2lo(p0, p1);
            pl[b][o + 1] = pack2lo(p2, p3);
        }

        const uint32_t vb = sb + AV_OFF(st);
#pragma unroll
        for (int b = 0; b < 2; ++b) {
            int kcol = wc * 32 + b * 16;
            uint32_t v[4][4];
#pragma unroll
            for (int dnb = 0; dnb < 4; ++dnb) {
                int nn = dnb * 16 + (lid & 7) + ((lid >> 4) & 1) * 8;
                int kk = kcol + (((lid >> 3) & 1) << 3);
                ldsm4(v[dnb][0], v[dnb][1], v[dnb][2], v[dnb][3],
                      vb + nn * 272 + kk * 2);          // V hi
            }
#pragma unroll
            for (int n8 = 0; n8 < 8; ++n8) {
                mma16816(oacc[n8], ph[b], v[n8 >> 1][(n8 & 1) * 2],
                         v[n8 >> 1][(n8 & 1) * 2 + 1]);
                mma16816(oacc[n8], pl[b], v[n8 >> 1][(n8 & 1) * 2],
                         v[n8 >> 1][(n8 & 1) * 2 + 1]);
            }
#pragma unroll
            for (int dnb = 0; dnb < 4; ++dnb) {
                int nn = dnb * 16 + (lid & 7) + ((lid >> 4) & 1) * 8;
                int kk = kcol + (((lid >> 3) & 1) << 3);
                ldsm4(v[dnb][0], v[dnb][1], v[dnb][2], v[dnb][3],
                      vb + nn * 272 + 128 + kk * 2);    // V lo
            }
#pragma unroll
            for (int n8 = 0; n8 < 8; ++n8)
                mma16816(oacc[n8], ph[b], v[n8 >> 1][(n8 & 1) * 2],
                         v[n8 >> 1][(n8 & 1) * 2 + 1]);
        }
        __syncthreads();
    }
#undef ISSUE_KV

    // ---- merge halves, normalize, write [hi|lo] operand rows ----
    sum0 += __shfl_xor_sync(0xffffffffu, sum0, 1);
    sum0 += __shfl_xor_sync(0xffffffffu, sum0, 2);
    sum1 += __shfl_xor_sync(0xffffffffu, sum1, 1);
    sum1 += __shfl_xor_sync(0xffffffffu, sum1, 2);
    if ((lid & 3) == 0) {
        sSum[wc * 64 + rlo] = sum0;
        sSum[wc * 64 + rhi] = sum1;
        sM[wc * 64 + rlo] = m0;
        sM[wc * 64 + rhi] = m1;
    }
    if (wc == 1) {
#pragma unroll
        for (int i = 0; i < 8; i++) {
            int d = i * 8 + 2 * (lid & 3);
            sO[rlo * 64 + d] = oacc[i][0];
            sO[rlo * 64 + d + 1] = oacc[i][1];
            sO[rhi * 64 + d] = oacc[i][2];
            sO[rhi * 64 + d + 1] = oacc[i][3];
        }
    }
    __syncthreads();
    if (wc == 0) {
        float mo0 = sM[64 + rlo], mo1 = sM[64 + rhi];
        float M0 = fmaxf(m0, mo0), M1 = fmaxf(m1, mo1);
        float fs0 = __expf(m0 - M0), fo0 = __expf(mo0 - M0);
        float fs1 = __expf(m1 - M1), fo1 = __expf(mo1 - M1);
        float inv0 = 1.f / (sSum[rlo] * fs0 + sSum[64 + rlo] * fo0);
        float inv1 = 1.f / (sSum[rhi] * fs1 + sSum[64 + rhi] * fo1);
        __nv_bfloat16* outLo = g_acat + ((size_t)(n * TSEQ) + q0 + rlo) * GKD + h * HD;
        __nv_bfloat16* outHi = g_acat + ((size_t)(n * TSEQ) + q0 + rhi) * GKD + h * HD;
#pragma unroll
        for (int i = 0; i < 8; i++) {
            int d = i * 8 + 2 * (lid & 3);
            float v0 = (oacc[i][0] * fs0 + sO[rlo * 64 + d] * fo0) * inv0;
            float v1 = (oacc[i][1] * fs0 + sO[rlo * 64 + d + 1] * fo0) * inv0;
            float v2 = (oacc[i][2] * fs1 + sO[rhi * 64 + d] * fo1) * inv1;
            float v3 = (oacc[i][3] * fs1 + sO[rhi * 64 + d + 1] * fo1) * inv1;
            uint32_t h01 = pack2(v0, v1), l01 = pack2lo(v0, v1);
            uint32_t h23 = pack2(v2, v3), l23 = pack2lo(v2, v3);
            *(uint32_t*)(outLo + d)       = h01;
            *(uint32_t*)(outLo + d + 512) = l01;
            *(uint32_t*)(outHi + d)       = h23;
            *(uint32_t*)(outHi + d + 512) = l23;
        }
    }
}

// ---------------- launcher ---------------------------------------------------
extern "C" void kernel_launch(void* const* d_in, const int* in_sizes, int n_in,
                              void* d_out, int out_size) {
    (void)in_sizes; (void)n_in; (void)out_size;
    const float* x    = (const float*)d_in[0];
    const float* Wqkv = (const float*)d_in[1];
    const float* Wout = (const float*)d_in[2];
    const float* bout = (const float*)d_in[3];
    float* out = (float*)d_out;

    float* qkv_ptr = nullptr;
    cudaGetSymbolAddress((void**)&qkv_ptr, g_qkv);
    __nv_bfloat16 *xcat, *acat, *wqcat, *wocat;
    cudaGetSymbolAddress((void**)&xcat, g_xcat);
    cudaGetSymbolAddress((void**)&acat, g_acat);
    cudaGetSymbolAddress((void**)&wqcat, g_wqcat);
    cudaGetSymbolAddress((void**)&wocat, g_wocat);

    cudaFuncSetAttribute(attn_flash_kernel,
                         cudaFuncAttributeMaxDynamicSharedMemorySize,
                         AFL_SMEM);

    rope_table_kernel<<<(TSEQ * 32 + 255) / 256, 256>>>();

    split_kernel<<<(MTOT * 128 + 255) / 256, 256>>>(x, xcat, MTOT * 128);
    split_kernel<<<(EQKV * 128 + 255) / 256, 256>>>(Wqkv, wqcat, EQKV * 128);
    split_kernel<<<(DM * 128 + 255) / 256, 256>>>(Wout, wocat, DM * 128);

    // qkv = x @ Wqkv^T  (split-bf16 HMMA, de-duplicated operands)
    gemm_mma<false><<<dim3(EQKV / 128, MTOT / 128), 256>>>(
        xcat, wqcat, nullptr, qkv_ptr, EQKV);

    // fused RoPE + V transpose
    prep_kernel<<<dim3(TSEQ / 32, NB * NH), 256>>>();

    // attention writes [hi|lo] operand rows directly
    attn_flash_kernel<<<dim3(TSEQ / QT, NB * NH), 256, AFL_SMEM>>>();

    // out = attn @ Wout^T + bout
    gemm_mma<true><<<dim3(DM / 128, MTOT / 128), 256>>>(
        acat, wocat, bout, out, DM);
}

// round 15
// speedup vs baseline: 1.7853x; 1.0426x over previous
#include <cuda_runtime.h>
#include <cuda_bf16.h>
#include <math.h>
#include <stdint.h>

#define NB 8
#define TSEQ 2048
#define DM 512
#define NH 8
#define HD 64
#define MTOT (NB * TSEQ)          // 16384
#define EQKV (3 * DM)             // 1536
#define GKD 1024                  // GEMM operand row: [hi 512 | lo 512] bf16

#define QT 64

// ---- flash attention smem layout (bytes); Q/K rows are [hi 64 | lo 64] ----
#define AQ_OFF   0                         // 64 x 128 bf16, pitch 272B = 17408
#define AK_OFF(s) (17408 + (s) * 34816)    // 64 x 128 bf16 K tile, pitch 272B
#define AV_OFF(s) (AK_OFF(s) + 17408)      // 64 x 128 bf16 V tile (hi|lo), pitch 272B
#define AM_OFF    87040                    // 2 x 64 fp32 (per-half running max)
#define ASUM_OFF  87552                    // 2 x 64 fp32
#define AO_OFF    17408                    // 64 x 64 fp32 exchange (overlays stage0 K)
#define AFL_SMEM  88064

// ---------------- scratch (device globals) ----------------------------------
__device__ float g_qkv[(size_t)MTOT * EQKV];
__device__ float g_cos[TSEQ * 32];
__device__ float g_sin[TSEQ * 32];
__device__ __nv_bfloat16 g_Qc[(size_t)NB * NH * TSEQ * 128];  // [Qh|Ql]
__device__ __nv_bfloat16 g_Kc[(size_t)NB * NH * TSEQ * 128];  // [Kh|Kl]
__device__ __nv_bfloat16 g_Vth[(size_t)NB * NH * HD * TSEQ];  // V^T hi [d][t]
__device__ __nv_bfloat16 g_Vtl[(size_t)NB * NH * HD * TSEQ];  // V^T lo [d][t]
__device__ __nv_bfloat16 g_xcat[(size_t)MTOT * GKD];          // x [hi|lo]
__device__ __nv_bfloat16 g_acat[(size_t)MTOT * GKD];          // attn out [hi|lo]
__device__ __nv_bfloat16 g_wqcat[(size_t)EQKV * GKD];
__device__ __nv_bfloat16 g_wocat[(size_t)DM * GKD];

// ---------------- helpers ----------------------------------------------------
__device__ __forceinline__ uint32_t smem_u32(const void* p) {
    uint32_t a;
    asm("{ .reg .u64 t; cvta.to.shared.u64 t, %1; cvt.u32.u64 %0, t; }"
        : "=r"(a) : "l"(p));
    return a;
}

__device__ __forceinline__ void cp16(uint32_t dst, const void* src) {
    asm volatile("cp.async.cg.shared.global [%0], [%1], 16;"
                 :: "r"(dst), "l"(src) : "memory");
}

__device__ __forceinline__ void ldsm4(uint32_t& r0, uint32_t& r1,
                                      uint32_t& r2, uint32_t& r3, uint32_t addr) {
    asm volatile("ldmatrix.sync.aligned.m8n8.x4.shared.b16 {%0,%1,%2,%3}, [%4];"
                 : "=r"(r0), "=r"(r1), "=r"(r2), "=r"(r3) : "r"(addr));
}

__device__ __forceinline__ void mma16816(float* c, const uint32_t* a,
                                         uint32_t b0, uint32_t b1) {
    asm volatile(
        "mma.sync.aligned.m16n8k16.row.col.f32.bf16.bf16.f32 "
        "{%0,%1,%2,%3}, {%4,%5,%6,%7}, {%8,%9}, {%0,%1,%2,%3};"
        : "+f"(c[0]), "+f"(c[1]), "+f"(c[2]), "+f"(c[3])
        : "r"(a[0]), "r"(a[1]), "r"(a[2]), "r"(a[3]), "r"(b0), "r"(b1));
}

__device__ __forceinline__ void split1(float x, __nv_bfloat16& h, __nv_bfloat16& l) {
    h = __float2bfloat16(x);
    l = __float2bfloat16(x - __bfloat162float(h));
}

__device__ __forceinline__ uint16_t bfbits(__nv_bfloat16 b) {
    return *reinterpret_cast<uint16_t*>(&b);
}

__device__ __forceinline__ uint32_t pack2(float a, float b) {
    __nv_bfloat16 ha = __float2bfloat16(a), hb = __float2bfloat16(b);
    return (uint32_t)bfbits(ha) | ((uint32_t)bfbits(hb) << 16);
}

// pack the bf16 lo-residuals of a,b
__device__ __forceinline__ uint32_t pack2lo(float a, float b) {
    __nv_bfloat16 ha = __float2bfloat16(a), hb = __float2bfloat16(b);
    __nv_bfloat16 la = __float2bfloat16(a - __bfloat162float(ha));
    __nv_bfloat16 lb = __float2bfloat16(b - __bfloat162float(hb));
    return (uint32_t)bfbits(la) | ((uint32_t)bfbits(lb) << 16);
}

// ---------------- split-bf16 GEMM, de-duplicated operands (R13) -------------
#define SROW 40
#define TILE_B (128 * SROW * 2)     // 10240 bytes per tile
#define STG (4 * TILE_B)            // 40960 bytes per stage

template <bool BIAS>
__global__ __launch_bounds__(256, 2)
void gemm_mma(const __nv_bfloat16* __restrict__ A, const __nv_bfloat16* __restrict__ B,
              const float* __restrict__ bias, float* __restrict__ C, int N) {
    __shared__ __nv_bfloat16 smem_t[2][4][128 * SROW];   // [stage][AH,AL,BH,BL]

    const int tid = threadIdx.x;
    const int lid = tid & 31;
    const int wid = tid >> 5;
    const int wm = wid >> 2;
    const int wn = wid & 3;
    const int m0 = blockIdx.y * 128;
    const int n0 = blockIdx.x * 128;
    const uint32_t smb = smem_u32(smem_t);

    float acc[4][4][4];
#pragma unroll
    for (int i = 0; i < 4; i++)
#pragma unroll
        for (int j = 0; j < 4; j++)
#pragma unroll
            for (int q = 0; q < 4; q++) acc[i][j][q] = 0.f;

#define PREFETCH(st_, kt_)                                                      \
    {                                                                           \
        _Pragma("unroll")                                                       \
        for (int i = 0; i < 8; ++i) {                                           \
            int u = tid + i * 256;                                              \
            int tile = u >> 9;                                                  \
            int v = u & 511;                                                    \
            int row = v >> 2, c = v & 3;                                        \
            const __nv_bfloat16* src =                                          \
                (tile < 2 ? A + (size_t)(m0 + row) * GKD                        \
                          : B + (size_t)(n0 + row) * GKD)                       \
                + (tile & 1) * 512 + (kt_) * 32 + c * 8;                        \
            cp16(smb + (st_) * STG + tile * TILE_B + row * 80 + c * 16, src);   \
        }                                                                       \
        asm volatile("cp.async.commit_group;" ::: "memory");                    \
    }

    const int NKT = 16;
    PREFETCH(0, 0);

    for (int kt = 0; kt < NKT; ++kt) {
        const int st = kt & 1;
        if (kt + 1 < NKT) {
            PREFETCH(st ^ 1, kt + 1);
            asm volatile("cp.async.wait_group 1;" ::: "memory");
        } else {
            asm volatile("cp.async.wait_group 0;" ::: "memory");
        }
        __syncthreads();

        const uint32_t sAH = smb + st * STG;
        const uint32_t sAL = sAH + TILE_B;
        const uint32_t sBH = sAL + TILE_B;
        const uint32_t sBL = sBH + TILE_B;

#pragma unroll
        for (int ks = 0; ks < 32; ks += 16) {
            uint32_t a[4][4], bh[2][4], bl[2][4];
#pragma unroll
            for (int nb = 0; nb < 2; ++nb) {
                int n = wn * 32 + nb * 16 + (lid & 7) + ((lid >> 4) & 1) * 8;
                int ke = ks + (((lid >> 3) & 1) << 3);
                ldsm4(bh[nb][0], bh[nb][1], bh[nb][2], bh[nb][3],
                      sBH + (uint32_t)(n * SROW + ke) * 2);
                ldsm4(bl[nb][0], bl[nb][1], bl[nb][2], bl[nb][3],
                      sBL + (uint32_t)(n * SROW + ke) * 2);
            }
#pragma unroll
            for (int mi = 0; mi < 4; ++mi) {
                int row = wm * 64 + mi * 16 + (lid & 7) + ((lid >> 3) & 1) * 8;
                int ke = ks + ((lid >> 4) << 3);
                ldsm4(a[mi][0], a[mi][1], a[mi][2], a[mi][3],
                      sAH + (uint32_t)(row * SROW + ke) * 2);
            }
#pragma unroll
            for (int mi = 0; mi < 4; ++mi)
#pragma unroll
                for (int nf = 0; nf < 4; ++nf) {
                    mma16816(acc[mi][nf], a[mi],
                             bh[nf >> 1][(nf & 1) * 2], bh[nf >> 1][(nf & 1) * 2 + 1]);
                    mma16816(acc[mi][nf], a[mi],
                             bl[nf >> 1][(nf & 1) * 2], bl[nf >> 1][(nf & 1) * 2 + 1]);
                }
#pragma unroll
            for (int mi = 0; mi < 4; ++mi) {
                int row = wm * 64 + mi * 16 + (lid & 7) + ((lid >> 3) & 1) * 8;
                int ke = ks + ((lid >> 4) << 3);
                ldsm4(a[mi][0], a[mi][1], a[mi][2], a[mi][3],
                      sAL + (uint32_t)(row * SROW + ke) * 2);
            }
#pragma unroll
            for (int mi = 0; mi < 4; ++mi)
#pragma unroll
                for (int nf = 0; nf < 4; ++nf)
                    mma16816(acc[mi][nf], a[mi],
                             bh[nf >> 1][(nf & 1) * 2], bh[nf >> 1][(nf & 1) * 2 + 1]);
        }
        __syncthreads();
    }

    const int r = lid >> 2;
    const int cc = (lid & 3) * 2;
#pragma unroll
    for (int mi = 0; mi < 4; ++mi) {
#pragma unroll
        for (int nf = 0; nf < 4; ++nf) {
            int row = m0 + wm * 64 + mi * 16 + r;
            int col = n0 + wn * 32 + nf * 8 + cc;
            float bx = 0.f, by = 0.f;
            if (BIAS) { bx = bias[col]; by = bias[col + 1]; }
            float2 v0 = make_float2(acc[mi][nf][0] + bx, acc[mi][nf][1] + by);
            float2 v1 = make_float2(acc[mi][nf][2] + bx, acc[mi][nf][3] + by);
            *(float2*)(C + (size_t)row * N + col) = v0;
            *(float2*)(C + (size_t)(row + 8) * N + col) = v1;
        }
    }
#undef PREFETCH
}

// ---------------- fp32 -> [hi|lo] split -------------------------------------
__global__ void split_kernel(const float* __restrict__ src,
                             __nv_bfloat16* __restrict__ dst, int total4) {
    int i = blockIdx.x * blockDim.x + threadIdx.x;
    if (i >= total4) return;
    int row = i >> 7;
    int c4 = i & 127;
    float4 v = ((const float4*)src)[i];
    __nv_bfloat16 h[4], l[4];
    split1(v.x, h[0], l[0]);
    split1(v.y, h[1], l[1]);
    split1(v.z, h[2], l[2]);
    split1(v.w, h[3], l[3]);
    __nv_bfloat16* d = dst + (size_t)row * GKD + c4 * 4;
    *(uint64_t*)(d)       = *(uint64_t*)h;
    *(uint64_t*)(d + 512) = *(uint64_t*)l;
}

// ---------------- RoPE table ------------------------------------------------
__global__ void rope_table_kernel() {
    int idx = blockIdx.x * blockDim.x + threadIdx.x;
    if (idx >= TSEQ * 32) return;
    int t = idx >> 5;
    int j = idx & 31;
    double inv = exp(-log(10000.0) * (double)j / 32.0);
    float ang = (float)t * (float)inv;
    g_cos[idx] = (float)cos((double)ang);
    g_sin[idx] = (float)sin((double)ang);
}

// ---------------- fused RoPE(Q,K) + V transpose/split -----------------------
__global__ void prep_kernel() {
    __shared__ __nv_bfloat16 svh[64 * 33];
    __shared__ __nv_bfloat16 svl[64 * 33];
    const int tid = threadIdx.x;
    const int nh = blockIdx.y;
    const int n = nh >> 3, h = nh & 7;
    const int t0 = blockIdx.x * 32;

#pragma unroll
    for (int it = 0; it < 4; ++it) {
        int e = tid + it * 256;
        int t = t0 + (e >> 5);
        int j = e & 31;

        const float* base = g_qkv + (size_t)(n * TSEQ + t) * EQKV;
        float c = g_cos[t * 32 + j];
        float s = g_sin[t * 32 + j];

        float q1 = base[h * HD + j];
        float q2 = base[h * HD + j + 32];
        float k1 = base[DM + h * HD + j];
        float k2 = base[DM + h * HD + j + 32];

        float q1r = q1 * c - q2 * s;
        float q2r = q2 * c + q1 * s;
        float k1r = k1 * c - k2 * s;
        float k2r = k2 * c + k1 * s;

        __nv_bfloat16 h1, l1, h2, l2;
        __nv_bfloat16* qrow = g_Qc + ((size_t)nh * TSEQ + t) * 128;
        split1(q1r, h1, l1); split1(q2r, h2, l2);
        qrow[j]      = h1; qrow[64 + j] = l1;
        qrow[32 + j] = h2; qrow[96 + j] = l2;

        __nv_bfloat16* krow = g_Kc + ((size_t)nh * TSEQ + t) * 128;
        split1(k1r, h1, l1); split1(k2r, h2, l2);
        krow[j]      = h1; krow[64 + j] = l1;
        krow[32 + j] = h2; krow[96 + j] = l2;
    }

#pragma unroll
    for (int i = 0; i < 8; i++) {
        int e = tid + i * 256;
        int tl = e >> 6, d = e & 63;
        float v = g_qkv[(size_t)(n * TSEQ + t0 + tl) * EQKV + 2 * DM + h * HD + d];
        __nv_bfloat16 hb, lb;
        split1(v, hb, lb);
        svh[d * 33 + tl] = hb;
        svl[d * 33 + tl] = lb;
    }
    __syncthreads();
#pragma unroll
    for (int i = 0; i < 8; i++) {
        int e = tid + i * 256;
        int d = e >> 5, tl = e & 31;
        size_t o = ((size_t)nh * HD + d) * TSEQ + t0 + tl;
        g_Vth[o] = svh[d * 33 + tl];
        g_Vtl[o] = svl[d * 33 + tl];
    }
}

// ---------------- flash-style banded attention (dedup Q/K) ------------------
// CTA per (n*NH+h, 64-q tile). 8 warps: wr = row slice (4), wc = j-half (2).
// S = Qh·Kh + Qh·Kl + Ql·Kh via register-level term passes.
__global__ __launch_bounds__(256, 2)
void attn_flash_kernel() {
    extern __shared__ char smc[];
    const uint32_t sb = smem_u32(smc);
    float* sM   = (float*)(smc + AM_OFF);       // [2][64]
    float* sSum = (float*)(smc + ASUM_OFF);     // [2][64]
    float* sO   = (float*)(smc + AO_OFF);       // [64][64]

    const int tid = threadIdx.x;
    const int lid = tid & 31, wid = tid >> 5;
    const int wr = wid & 3, wc = wid >> 2;
    const int q0 = blockIdx.x * QT;
    const int nh = blockIdx.y;
    const int n = nh >> 3, h = nh & 7;
    const int ks = q0 - 128;
    const float scale = 0.125f;

    const int rlo = wr * 16 + (lid >> 2);
    const int rhi = rlo + 8;

    // ---- Q tile: 64 rows x 256B ----
#pragma unroll
    for (int i = 0; i < 4; i++) {
        int u = tid + i * 256;
        int r = u >> 4, c = u & 15;
        cp16(sb + AQ_OFF + r * 272 + c * 16,
             g_Qc + ((size_t)nh * TSEQ + q0 + r) * 128 + c * 8);
    }

#define ISSUE_KV(jt_, st_)                                                      \
    {                                                                           \
        _Pragma("unroll")                                                       \
        for (int i = 0; i < 4; i++) {                                           \
            int u = tid + i * 256;                                              \
            int r = u >> 4, c = u & 15;                                         \
            int j = ks + (jt_) * 64 + r;                                        \
            j = j < 0 ? 0 : (j > TSEQ - 1 ? TSEQ - 1 : j);                      \
            cp16(sb + AK_OFF(st_) + r * 272 + c * 16,                           \
                 g_Kc + ((size_t)nh * TSEQ + j) * 128 + c * 8);                 \
        }                                                                       \
        _Pragma("unroll")                                                       \
        for (int i = 0; i < 4; i++) {                                           \
            int u = tid + i * 256;                                              \
            int r = u >> 4, c = u & 15;                                         \
            int jb = ks + (jt_) * 64 + (c & 7) * 8;                             \
            jb = jb < 0 ? 0 : (jb > TSEQ - 8 ? TSEQ - 8 : jb);                  \
            const __nv_bfloat16* vs = (c < 8) ? g_Vth : g_Vtl;                  \
            cp16(sb + AV_OFF(st_) + r * 272 + c * 16,                           \
                 vs + ((size_t)nh * HD + r) * TSEQ + jb);                       \
        }                                                                       \
        asm volatile("cp.async.commit_group;" ::: "memory");                    \
    }

    ISSUE_KV(0, 0);

    float oacc[8][4];
#pragma unroll
    for (int i = 0; i < 8; i++)
#pragma unroll
        for (int q = 0; q < 4; q++) oacc[i][q] = 0.f;
    float m0 = -1e30f, m1 = -1e30f;
    float sum0 = 0.f, sum1 = 0.f;

    for (int jt = 0; jt < 5; ++jt) {
        const int st = jt & 1;
        if (jt < 4) {
            ISSUE_KV(jt + 1, st ^ 1);
            asm volatile("cp.async.wait_group 1;" ::: "memory");
        } else {
            asm volatile("cp.async.wait_group 0;" ::: "memory");
        }
        __syncthreads();

        // ---- S = Qh·Kh + Qh·Kl + Ql·Kh (16 rows x 32 cols per warp) ----
        float sacc[4][4];
#pragma unroll
        for (int i = 0; i < 4; i++)
#pragma unroll
            for (int q = 0; q < 4; q++) sacc[i][q] = 0.f;

        const uint32_t kb = sb + AK_OFF(st);
#pragma unroll
        for (int k4 = 0; k4 < 4; ++k4) {
            uint32_t ah[4], al[4], bh[2][4], bl[2][4];
            {
                int row = wr * 16 + (lid & 7) + ((lid >> 3) & 1) * 8;
                int ke = k4 * 16 + ((lid >> 4) << 3);
                ldsm4(ah[0], ah[1], ah[2], ah[3],
                      sb + AQ_OFF + row * 272 + ke * 2);
                ldsm4(al[0], al[1], al[2], al[3],
                      sb + AQ_OFF + row * 272 + (ke + 64) * 2);
            }
#pragma unroll
            for (int nb = 0; nb < 2; ++nb) {
                int nn = wc * 32 + nb * 16 + (lid & 7) + ((lid >> 4) & 1) * 8;
                int ke = k4 * 16 + (((lid >> 3) & 1) << 3);
                ldsm4(bh[nb][0], bh[nb][1], bh[nb][2], bh[nb][3],
                      kb + nn * 272 + ke * 2);
                ldsm4(bl[nb][0], bl[nb][1], bl[nb][2], bl[nb][3],
                      kb + nn * 272 + (ke + 64) * 2);
            }
#pragma unroll
            for (int nf = 0; nf < 4; ++nf) {
                mma16816(sacc[nf], ah, bh[nf >> 1][(nf & 1) * 2],
                         bh[nf >> 1][(nf & 1) * 2 + 1]);
                mma16816(sacc[nf], ah, bl[nf >> 1][(nf & 1) * 2],
                         bl[nf >> 1][(nf & 1) * 2 + 1]);
                mma16816(sacc[nf], al, bh[nf >> 1][(nf & 1) * 2],
                         bh[nf >> 1][(nf & 1) * 2 + 1]);
            }
        }

        // ---- mask + scale in regs ----
#pragma unroll
        for (int nf = 0; nf < 4; ++nf) {
#pragma unroll
            for (int e = 0; e < 2; ++e) {
                int j = ks + jt * 64 + wc * 32 + nf * 8 + 2 * (lid & 3) + e;
                int d0 = j - (q0 + rlo);
                int d1 = j - (q0 + rhi);
                bool in = (j >= 0) && (j < TSEQ);
                sacc[nf][e]     = (in && d0 >= -127 && d0 <= 128)
                                  ? sacc[nf][e] * scale : -1e30f;
                sacc[nf][2 + e] = (in && d1 >= -127 && d1 <= 128)
                                  ? sacc[nf][2 + e] * scale : -1e30f;
            }
        }

        // ---- per-half online softmax ----
        float mx0 = sacc[0][0], mx1 = sacc[0][2];
#pragma unroll
        for (int nf = 0; nf < 4; ++nf) {
            mx0 = fmaxf(mx0, fmaxf(sacc[nf][0], sacc[nf][1]));
            mx1 = fmaxf(mx1, fmaxf(sacc[nf][2], sacc[nf][3]));
        }
        mx0 = fmaxf(mx0, __shfl_xor_sync(0xffffffffu, mx0, 1));
        mx0 = fmaxf(mx0, __shfl_xor_sync(0xffffffffu, mx0, 2));
        mx1 = fmaxf(mx1, __shfl_xor_sync(0xffffffffu, mx1, 1));
        mx1 = fmaxf(mx1, __shfl_xor_sync(0xffffffffu, mx1, 2));
        float nm0 = fmaxf(m0, mx0);
        float nm1 = fmaxf(m1, mx1);
        float f0 = __expf(m0 - nm0);
        float f1 = __expf(m1 - nm1);
        m0 = nm0; m1 = nm1;
        sum0 *= f0; sum1 *= f1;
#pragma unroll
        for (int i = 0; i < 8; i++) {
            oacc[i][0] *= f0; oacc[i][1] *= f0;
            oacc[i][2] *= f1; oacc[i][3] *= f1;
        }

        // ---- P = exp(S - m); pack to bf16 hi/lo A-frags ----
        uint32_t ph[2][4], pl[2][4];
#pragma unroll
        for (int nf = 0; nf < 4; ++nf) {
            float p0 = __expf(sacc[nf][0] - nm0);
            float p1 = __expf(sacc[nf][1] - nm0);
            float p2 = __expf(sacc[nf][2] - nm1);
            float p3 = __expf(sacc[nf][3] - nm1);
            sum0 += p0 + p1;
            sum1 += p2 + p3;
            int b = nf >> 1;
            int o = (nf & 1) * 2;
            ph[b][o]     = pack2(p0, p1);
            ph[b][o + 1] = pack2(p2, p3);
            pl[b][o]     = pack2lo(p0, p1);
            pl[b][o + 1] = pack2lo(p2, p3);
        }

        // ---- O += Pcat · Vcat (3-term split, V already dedup'd) ----
        const uint32_t vb = sb + AV_OFF(st);
#pragma unroll
        for (int b = 0; b < 2; ++b) {
            int kcol = wc * 32 + b * 16;
            uint32_t v[4][4];
#pragma unroll
            for (int dnb = 0; dnb < 4; ++dnb) {
                int nn = dnb * 16 + (lid & 7) + ((lid >> 4) & 1) * 8;
                int kk = kcol + (((lid >> 3) & 1) << 3);
                ldsm4(v[dnb][0], v[dnb][1], v[dnb][2], v[dnb][3],
                      vb + nn * 272 + kk * 2);          // V hi
            }
#pragma unroll
            for (int n8 = 0; n8 < 8; ++n8) {
                mma16816(oacc[n8], ph[b], v[n8 >> 1][(n8 & 1) * 2],
                         v[n8 >> 1][(n8 & 1) * 2 + 1]);
                mma16816(oacc[n8], pl[b], v[n8 >> 1][(n8 & 1) * 2],
                         v[n8 >> 1][(n8 & 1) * 2 + 1]);
            }
#pragma unroll
            for (int dnb = 0; dnb < 4; ++dnb) {
                int nn = dnb * 16 + (lid & 7) + ((lid >> 4) & 1) * 8;
                int kk = kcol + (((lid >> 3) & 1) << 3);
                ldsm4(v[dnb][0], v[dnb][1], v[dnb][2], v[dnb][3],
                      vb + nn * 272 + 128 + kk * 2);    // V lo
            }
#pragma unroll
            for (int n8 = 0; n8 < 8; ++n8)
                mma16816(oacc[n8], ph[b], v[n8 >> 1][(n8 & 1) * 2],
                         v[n8 >> 1][(n8 & 1) * 2 + 1]);
        }
        __syncthreads();
    }
#undef ISSUE_KV

    // ---- merge halves, normalize, write [hi|lo] operand rows ----
    sum0 += __shfl_xor_sync(0xffffffffu, sum0, 1);
    sum0 += __shfl_xor_sync(0xffffffffu, sum0, 2);
    sum1 += __shfl_xor_sync(0xffffffffu, sum1, 1);
    sum1 += __shfl_xor_sync(0xffffffffu, sum1, 2);
    if ((lid & 3) == 0) {
        sSum[wc * 64 + rlo] = sum0;
        sSum[wc * 64 + rhi] = sum1;
        sM[wc * 64 + rlo] = m0;
        sM[wc * 64 + rhi] = m1;
    }
    if (wc == 1) {
#pragma unroll
        for (int i = 0; i < 8; i++) {
            int d = i * 8 + 2 * (lid & 3);
            sO[rlo * 64 + d] = oacc[i][0];
            sO[rlo * 64 + d + 1] = oacc[i][1];
            sO[rhi * 64 + d] = oacc[i][2];
            sO[rhi * 64 + d + 1] = oacc[i][3];
        }
    }
    __syncthreads();
    if (wc == 0) {
        float mo0 = sM[64 + rlo], mo1 = sM[64 + rhi];
        float M0 = fmaxf(m0, mo0), M1 = fmaxf(m1, mo1);
        float fs0 = __expf(m0 - M0), fo0 = __expf(mo0 - M0);
        float fs1 = __expf(m1 - M1), fo1 = __expf(mo1 - M1);
        float inv0 = 1.f / (sSum[rlo] * fs0 + sSum[64 + rlo] * fo0);
        float inv1 = 1.f / (sSum[rhi] * fs1 + sSum[64 + rhi] * fo1);
        __nv_bfloat16* outLo = g_acat + ((size_t)(n * TSEQ) + q0 + rlo) * GKD + h * HD;
        __nv_bfloat16* outHi = g_acat + ((size_t)(n * TSEQ) + q0 + rhi) * GKD + h * HD;
#pragma unroll
        for (int i = 0; i < 8; i++) {
            int d = i * 8 + 2 * (lid & 3);
            float v0 = (oacc[i][0] * fs0 + sO[rlo * 64 + d] * fo0) * inv0;
            float v1 = (oacc[i][1] * fs0 + sO[rlo * 64 + d + 1] * fo0) * inv0;
            float v2 = (oacc[i][2] * fs1 + sO[rhi * 64 + d] * fo1) * inv1;
            float v3 = (oacc[i][3] * fs1 + sO[rhi * 64 + d + 1] * fo1) * inv1;
            uint32_t h01 = pack2(v0, v1), l01 = pack2lo(v0, v1);
            uint32_t h23 = pack2(v2, v3), l23 = pack2lo(v2, v3);
            *(uint32_t*)(outLo + d)       = h01;
            *(uint32_t*)(outLo + d + 512) = l01;
            *(uint32_t*)(outHi + d)       = h23;
            *(uint32_t*)(outHi + d + 512) = l23;
        }
    }
}

// ---------------- launcher ---------------------------------------------------
extern "C" void kernel_launch(void* const* d_in, const int* in_sizes, int n_in,
                              void* d_out, int out_size) {
    (void)in_sizes; (void)n_in; (void)out_size;
    const float* x    = (const float*)d_in[0];
    const float* Wqkv = (const float*)d_in[1];
    const float* Wout = (const float*)d_in[2];
    const float* bout = (const float*)d_in[3];
    float* out = (float*)d_out;

    float* qkv_ptr = nullptr;
    cudaGetSymbolAddress((void**)&qkv_ptr, g_qkv);
    __nv_bfloat16 *xcat, *acat, *wqcat, *wocat;
    cudaGetSymbolAddress((void**)&xcat, g_xcat);
    cudaGetSymbolAddress((void**)&acat, g_acat);
    cudaGetSymbolAddress((void**)&wqcat, g_wqcat);
    cudaGetSymbolAddress((void**)&wocat, g_wocat);

    cudaFuncSetAttribute(attn_flash_kernel,
                         cudaFuncAttributeMaxDynamicSharedMemorySize,
                         AFL_SMEM);

    rope_table_kernel<<<(TSEQ * 32 + 255) / 256, 256>>>();

    split_kernel<<<(MTOT * 128 + 255) / 256, 256>>>(x, xcat, MTOT * 128);
    split_kernel<<<(EQKV * 128 + 255) / 256, 256>>>(Wqkv, wqcat, EQKV * 128);
    split_kernel<<<(DM * 128 + 255) / 256, 256>>>(Wout, wocat, DM * 128);

    // qkv = x @ Wqkv^T  (split-bf16 HMMA, de-duplicated operands)
    gemm_mma<false><<<dim3(EQKV / 128, MTOT / 128), 256>>>(
        xcat, wqcat, nullptr, qkv_ptr, EQKV);

    // fused RoPE + V transpose
    prep_kernel<<<dim3(TSEQ / 32, NB * NH), 256>>>();

    // attention (dedup Q/K) writes [hi|lo] operand rows directly
    attn_flash_kernel<<<dim3(TSEQ / QT, NB * NH), 256, AFL_SMEM>>>();

    // out = attn @ Wout^T + bout
    gemm_mma<true><<<dim3(DM / 128, MTOT / 128), 256>>>(
        acat, wocat, bout, out, DM);
}

// round 17
// speedup vs baseline: 1.8015x; 1.0091x over previous
#include <cuda_runtime.h>
#include <cuda_bf16.h>
#include <math.h>
#include <stdint.h>

#define NB 8
#define TSEQ 2048
#define DM 512
#define NH 8
#define HD 64
#define MTOT (NB * TSEQ)          // 16384
#define EQKV (3 * DM)             // 1536
#define GKD 1024                  // GEMM operand row: [hi 512 | lo 512] bf16

#define QT 64

// ---- flash attention smem layout (bytes); Q/K rows are [hi 64 | lo 64] ----
#define AQ_OFF   0                         // 64 x 128 bf16, pitch 272B = 17408
#define AK_OFF(s) (17408 + (s) * 34816)    // 64 x 128 bf16 K tile, pitch 272B
#define AV_OFF(s) (AK_OFF(s) + 17408)      // 64 x 128 bf16 V tile (hi|lo), pitch 272B
#define AM_OFF    87040                    // 2 x 64 fp32 (per-half running max)
#define ASUM_OFF  87552                    // 2 x 64 fp32
#define AO_OFF    17408                    // 64 x 64 fp32 exchange (overlays stage0 K)
#define AFL_SMEM  88064

// ---------------- scratch (device globals) ----------------------------------
__device__ float g_qkv[(size_t)MTOT * EQKV];
__device__ float g_cos[TSEQ * 32];
__device__ float g_sin[TSEQ * 32];
__device__ __nv_bfloat16 g_Qc[(size_t)NB * NH * TSEQ * 128];  // [Qh|Ql]
__device__ __nv_bfloat16 g_Kc[(size_t)NB * NH * TSEQ * 128];  // [Kh|Kl]
__device__ __nv_bfloat16 g_Vth[(size_t)NB * NH * HD * TSEQ];  // V^T hi [d][t]
__device__ __nv_bfloat16 g_Vtl[(size_t)NB * NH * HD * TSEQ];  // V^T lo [d][t]
__device__ __nv_bfloat16 g_xcat[(size_t)MTOT * GKD];          // x [hi|lo]
__device__ __nv_bfloat16 g_acat[(size_t)MTOT * GKD];          // attn out [hi|lo]
__device__ __nv_bfloat16 g_wqcat[(size_t)EQKV * GKD];
__device__ __nv_bfloat16 g_wocat[(size_t)DM * GKD];

// ---------------- helpers ----------------------------------------------------
__device__ __forceinline__ uint32_t smem_u32(const void* p) {
    uint32_t a;
    asm("{ .reg .u64 t; cvta.to.shared.u64 t, %1; cvt.u32.u64 %0, t; }"
        : "=r"(a) : "l"(p));
    return a;
}

__device__ __forceinline__ void cp16(uint32_t dst, const void* src) {
    asm volatile("cp.async.cg.shared.global [%0], [%1], 16;"
                 :: "r"(dst), "l"(src) : "memory");
}

__device__ __forceinline__ void ldsm4(uint32_t& r0, uint32_t& r1,
                                      uint32_t& r2, uint32_t& r3, uint32_t addr) {
    asm volatile("ldmatrix.sync.aligned.m8n8.x4.shared.b16 {%0,%1,%2,%3}, [%4];"
                 : "=r"(r0), "=r"(r1), "=r"(r2), "=r"(r3) : "r"(addr));
}

__device__ __forceinline__ void mma16816(float* c, const uint32_t* a,
                                         uint32_t b0, uint32_t b1) {
    asm volatile(
        "mma.sync.aligned.m16n8k16.row.col.f32.bf16.bf16.f32 "
        "{%0,%1,%2,%3}, {%4,%5,%6,%7}, {%8,%9}, {%0,%1,%2,%3};"
        : "+f"(c[0]), "+f"(c[1]), "+f"(c[2]), "+f"(c[3])
        : "r"(a[0]), "r"(a[1]), "r"(a[2]), "r"(a[3]), "r"(b0), "r"(b1));
}

__device__ __forceinline__ float ex2(float x) {
    float r;
    asm("ex2.approx.f32 %0, %1;" : "=f"(r) : "f"(x));
    return r;
}

__device__ __forceinline__ void split1(float x, __nv_bfloat16& h, __nv_bfloat16& l) {
    h = __float2bfloat16(x);
    l = __float2bfloat16(x - __bfloat162float(h));
}

// one-instruction pack of two floats into bf16x2 (low half <- a, high <- b)
__device__ __forceinline__ uint32_t pack2(float a, float b) {
    uint32_t r;
    asm("cvt.rn.bf16x2.f32 %0, %1, %2;" : "=r"(r) : "f"(b), "f"(a));
    return r;
}

// fused hi/lo pack: hi word + residual word for pair (a,b)
__device__ __forceinline__ void pack_hl(float a, float b,
                                        uint32_t& hw, uint32_t& lw) {
    hw = pack2(a, b);
    float af = __uint_as_float(hw << 16);
    float bf = __uint_as_float(hw & 0xffff0000u);
    lw = pack2(a - af, b - bf);
}

// ---------------- split-bf16 GEMM, de-duplicated operands -------------------
#define SROW 40
#define TILE_B (128 * SROW * 2)     // 10240 bytes per tile
#define STG (4 * TILE_B)            // 40960 bytes per stage

template <bool BIAS>
__global__ __launch_bounds__(256, 2)
void gemm_mma(const __nv_bfloat16* __restrict__ A, const __nv_bfloat16* __restrict__ B,
              const float* __restrict__ bias, float* __restrict__ C, int N) {
    __shared__ __nv_bfloat16 smem_t[2][4][128 * SROW];   // [stage][AH,AL,BH,BL]

    const int tid = threadIdx.x;
    const int lid = tid & 31;
    const int wid = tid >> 5;
    const int wm = wid >> 2;
    const int wn = wid & 3;
    const int m0 = blockIdx.y * 128;
    const int n0 = blockIdx.x * 128;
    const uint32_t smb = smem_u32(smem_t);

    float acc[4][4][4];
#pragma unroll
    for (int i = 0; i < 4; i++)
#pragma unroll
        for (int j = 0; j < 4; j++)
#pragma unroll
            for (int q = 0; q < 4; q++) acc[i][j][q] = 0.f;

#define PREFETCH(st_, kt_)                                                      \
    {                                                                           \
        _Pragma("unroll")                                                       \
        for (int i = 0; i < 8; ++i) {                                           \
            int u = tid + i * 256;                                              \
            int tile = u >> 9;                                                  \
            int v = u & 511;                                                    \
            int row = v >> 2, c = v & 3;                                        \
            const __nv_bfloat16* src =                                          \
                (tile < 2 ? A + (size_t)(m0 + row) * GKD                        \
                          : B + (size_t)(n0 + row) * GKD)                       \
                + (tile & 1) * 512 + (kt_) * 32 + c * 8;                        \
            cp16(smb + (st_) * STG + tile * TILE_B + row * 80 + c * 16, src);   \
        }                                                                       \
        asm volatile("cp.async.commit_group;" ::: "memory");                    \
    }

    const int NKT = 16;
    PREFETCH(0, 0);

    for (int kt = 0; kt < NKT; ++kt) {
        const int st = kt & 1;
        if (kt + 1 < NKT) {
            PREFETCH(st ^ 1, kt + 1);
            asm volatile("cp.async.wait_group 1;" ::: "memory");
        } else {
            asm volatile("cp.async.wait_group 0;" ::: "memory");
        }
        __syncthreads();

        const uint32_t sAH = smb + st * STG;
        const uint32_t sAL = sAH + TILE_B;
        const uint32_t sBH = sAL + TILE_B;
        const uint32_t sBL = sBH + TILE_B;

#pragma unroll
        for (int ks = 0; ks < 32; ks += 16) {
            uint32_t a[4][4], bh[2][4], bl[2][4];
#pragma unroll
            for (int nb = 0; nb < 2; ++nb) {
                int n = wn * 32 + nb * 16 + (lid & 7) + ((lid >> 4) & 1) * 8;
                int ke = ks + (((lid >> 3) & 1) << 3);
                ldsm4(bh[nb][0], bh[nb][1], bh[nb][2], bh[nb][3],
                      sBH + (uint32_t)(n * SROW + ke) * 2);
                ldsm4(bl[nb][0], bl[nb][1], bl[nb][2], bl[nb][3],
                      sBL + (uint32_t)(n * SROW + ke) * 2);
            }
#pragma unroll
            for (int mi = 0; mi < 4; ++mi) {
                int row = wm * 64 + mi * 16 + (lid & 7) + ((lid >> 3) & 1) * 8;
                int ke = ks + ((lid >> 4) << 3);
                ldsm4(a[mi][0], a[mi][1], a[mi][2], a[mi][3],
                      sAH + (uint32_t)(row * SROW + ke) * 2);
            }
#pragma unroll
            for (int mi = 0; mi < 4; ++mi)
#pragma unroll
                for (int nf = 0; nf < 4; ++nf) {
                    mma16816(acc[mi][nf], a[mi],
                             bh[nf >> 1][(nf & 1) * 2], bh[nf >> 1][(nf & 1) * 2 + 1]);
                    mma16816(acc[mi][nf], a[mi],
                             bl[nf >> 1][(nf & 1) * 2], bl[nf >> 1][(nf & 1) * 2 + 1]);
                }
#pragma unroll
            for (int mi = 0; mi < 4; ++mi) {
                int row = wm * 64 + mi * 16 + (lid & 7) + ((lid >> 3) & 1) * 8;
                int ke = ks + ((lid >> 4) << 3);
                ldsm4(a[mi][0], a[mi][1], a[mi][2], a[mi][3],
                      sAL + (uint32_t)(row * SROW + ke) * 2);
            }
#pragma unroll
            for (int mi = 0; mi < 4; ++mi)
#pragma unroll
                for (int nf = 0; nf < 4; ++nf)
                    mma16816(acc[mi][nf], a[mi],
                             bh[nf >> 1][(nf & 1) * 2], bh[nf >> 1][(nf & 1) * 2 + 1]);
        }
        __syncthreads();
    }

    const int r = lid >> 2;
    const int cc = (lid & 3) * 2;
#pragma unroll
    for (int mi = 0; mi < 4; ++mi) {
#pragma unroll
        for (int nf = 0; nf < 4; ++nf) {
            int row = m0 + wm * 64 + mi * 16 + r;
            int col = n0 + wn * 32 + nf * 8 + cc;
            float bx = 0.f, by = 0.f;
            if (BIAS) { bx = bias[col]; by = bias[col + 1]; }
            float2 v0 = make_float2(acc[mi][nf][0] + bx, acc[mi][nf][1] + by);
            float2 v1 = make_float2(acc[mi][nf][2] + bx, acc[mi][nf][3] + by);
            *(float2*)(C + (size_t)row * N + col) = v0;
            *(float2*)(C + (size_t)(row + 8) * N + col) = v1;
        }
    }
#undef PREFETCH
}

// ---------------- fp32 -> [hi|lo] split -------------------------------------
__global__ void split_kernel(const float* __restrict__ src,
                             __nv_bfloat16* __restrict__ dst, int total4) {
    int i = blockIdx.x * blockDim.x + threadIdx.x;
    if (i >= total4) return;
    int row = i >> 7;
    int c4 = i & 127;
    float4 v = ((const float4*)src)[i];
    uint32_t h0, l0, h1, l1;
    pack_hl(v.x, v.y, h0, l0);
    pack_hl(v.z, v.w, h1, l1);
    __nv_bfloat16* d = dst + (size_t)row * GKD + c4 * 4;
    *(uint2*)(d)       = make_uint2(h0, h1);
    *(uint2*)(d + 512) = make_uint2(l0, l1);
}

// ---------------- RoPE table ------------------------------------------------
__global__ void rope_table_kernel() {
    int idx = blockIdx.x * blockDim.x + threadIdx.x;
    if (idx >= TSEQ * 32) return;
    int t = idx >> 5;
    int j = idx & 31;
    double inv = exp(-log(10000.0) * (double)j / 32.0);
    float ang = (float)t * (float)inv;
    g_cos[idx] = (float)cos((double)ang);
    g_sin[idx] = (float)sin((double)ang);
}

// ---------------- fused RoPE(Q,K) + V transpose/split -----------------------
__global__ void prep_kernel() {
    __shared__ __nv_bfloat16 svh[64 * 33];
    __shared__ __nv_bfloat16 svl[64 * 33];
    const int tid = threadIdx.x;
    const int nh = blockIdx.y;
    const int n = nh >> 3, h = nh & 7;
    const int t0 = blockIdx.x * 32;

#pragma unroll
    for (int it = 0; it < 4; ++it) {
        int e = tid + it * 256;
        int t = t0 + (e >> 5);
        int j = e & 31;

        const float* base = g_qkv + (size_t)(n * TSEQ + t) * EQKV;
        float c = g_cos[t * 32 + j];
        float s = g_sin[t * 32 + j];

        float q1 = base[h * HD + j];
        float q2 = base[h * HD + j + 32];
        float k1 = base[DM + h * HD + j];
        float k2 = base[DM + h * HD + j + 32];

        float q1r = q1 * c - q2 * s;
        float q2r = q2 * c + q1 * s;
        float k1r = k1 * c - k2 * s;
        float k2r = k2 * c + k1 * s;

        __nv_bfloat16 h1, l1, h2, l2;
        __nv_bfloat16* qrow = g_Qc + ((size_t)nh * TSEQ + t) * 128;
        split1(q1r, h1, l1); split1(q2r, h2, l2);
        qrow[j]      = h1; qrow[64 + j] = l1;
        qrow[32 + j] = h2; qrow[96 + j] = l2;

        __nv_bfloat16* krow = g_Kc + ((size_t)nh * TSEQ + t) * 128;
        split1(k1r, h1, l1); split1(k2r, h2, l2);
        krow[j]      = h1; krow[64 + j] = l1;
        krow[32 + j] = h2; krow[96 + j] = l2;
    }

#pragma unroll
    for (int i = 0; i < 8; i++) {
        int e = tid + i * 256;
        int tl = e >> 6, d = e & 63;
        float v = g_qkv[(size_t)(n * TSEQ + t0 + tl) * EQKV + 2 * DM + h * HD + d];
        __nv_bfloat16 hb, lb;
        split1(v, hb, lb);
        svh[d * 33 + tl] = hb;
        svl[d * 33 + tl] = lb;
    }
    __syncthreads();
#pragma unroll
    for (int i = 0; i < 8; i++) {
        int e = tid + i * 256;
        int d = e >> 5, tl = e & 31;
        size_t o = ((size_t)nh * HD + d) * TSEQ + t0 + tl;
        g_Vth[o] = svh[d * 33 + tl];
        g_Vtl[o] = svl[d * 33 + tl];
    }
}

// ---------------- flash-style banded attention (dedup Q/K, log2 softmax) ----
__global__ __launch_bounds__(256, 2)
void attn_flash_kernel() {
    extern __shared__ char smc[];
    const uint32_t sb = smem_u32(smc);
    float* sM   = (float*)(smc + AM_OFF);       // [2][64]
    float* sSum = (float*)(smc + ASUM_OFF);     // [2][64]
    float* sO   = (float*)(smc + AO_OFF);       // [64][64]

    const int tid = threadIdx.x;
    const int lid = tid & 31, wid = tid >> 5;
    const int wr = wid & 3, wc = wid >> 2;
    const int q0 = blockIdx.x * QT;
    const int nh = blockIdx.y;
    const int n = nh >> 3, h = nh & 7;
    const int ks = q0 - 128;
    const float SCL = 0.125f * 1.4426950408889634f;   // scale * log2(e)

    const int rlo = wr * 16 + (lid >> 2);
    const int rhi = rlo + 8;

    // ---- Q tile: 64 rows x 256B ----
#pragma unroll
    for (int i = 0; i < 4; i++) {
        int u = tid + i * 256;
        int r = u >> 4, c = u & 15;
        cp16(sb + AQ_OFF + r * 272 + c * 16,
             g_Qc + ((size_t)nh * TSEQ + q0 + r) * 128 + c * 8);
    }

#define ISSUE_KV(jt_, st_)                                                      \
    {                                                                           \
        _Pragma("unroll")                                                       \
        for (int i = 0; i < 4; i++) {                                           \
            int u = tid + i * 256;                                              \
            int r = u >> 4, c = u & 15;                                         \
            int j = ks + (jt_) * 64 + r;                                        \
            j = j < 0 ? 0 : (j > TSEQ - 1 ? TSEQ - 1 : j);                      \
            cp16(sb + AK_OFF(st_) + r * 272 + c * 16,                           \
                 g_Kc + ((size_t)nh * TSEQ + j) * 128 + c * 8);                 \
        }                                                                       \
        _Pragma("unroll")                                                       \
        for (int i = 0; i < 4; i++) {                                           \
            int u = tid + i * 256;                                              \
            int r = u >> 4, c = u & 15;                                         \
            int jb = ks + (jt_) * 64 + (c & 7) * 8;                             \
            jb = jb < 0 ? 0 : (jb > TSEQ - 8 ? TSEQ - 8 : jb);                  \
            const __nv_bfloat16* vs = (c < 8) ? g_Vth : g_Vtl;                  \
            cp16(sb + AV_OFF(st_) + r * 272 + c * 16,                           \
                 vs + ((size_t)nh * HD + r) * TSEQ + jb);                       \
        }                                                                       \
        asm volatile("cp.async.commit_group;" ::: "memory");                    \
    }

    ISSUE_KV(0, 0);

    float oacc[8][4];
#pragma unroll
    for (int i = 0; i < 8; i++)
#pragma unroll
        for (int q = 0; q < 4; q++) oacc[i][q] = 0.f;
    float m0 = -1e30f, m1 = -1e30f;
    float sum0 = 0.f, sum1 = 0.f;

    for (int jt = 0; jt < 5; ++jt) {
        const int st = jt & 1;
        if (jt < 4) {
            ISSUE_KV(jt + 1, st ^ 1);
            asm volatile("cp.async.wait_group 1;" ::: "memory");
        } else {
            asm volatile("cp.async.wait_group 0;" ::: "memory");
        }
        __syncthreads();

        // ---- S = Qh·Kh + Qh·Kl + Ql·Kh ----
        float sacc[4][4];
#pragma unroll
        for (int i = 0; i < 4; i++)
#pragma unroll
            for (int q = 0; q < 4; q++) sacc[i][q] = 0.f;

        const uint32_t kb = sb + AK_OFF(st);
#pragma unroll
        for (int k4 = 0; k4 < 4; ++k4) {
            uint32_t ah[4], al[4], bh[2][4], bl[2][4];
            {
                int row = wr * 16 + (lid & 7) + ((lid >> 3) & 1) * 8;
                int ke = k4 * 16 + ((lid >> 4) << 3);
                ldsm4(ah[0], ah[1], ah[2], ah[3],
                      sb + AQ_OFF + row * 272 + ke * 2);
                ldsm4(al[0], al[1], al[2], al[3],
                      sb + AQ_OFF + row * 272 + (ke + 64) * 2);
            }
#pragma unroll
            for (int nb = 0; nb < 2; ++nb) {
                int nn = wc * 32 + nb * 16 + (lid & 7) + ((lid >> 4) & 1) * 8;
                int ke = k4 * 16 + (((lid >> 3) & 1) << 3);
                ldsm4(bh[nb][0], bh[nb][1], bh[nb][2], bh[nb][3],
                      kb + nn * 272 + ke * 2);
                ldsm4(bl[nb][0], bl[nb][1], bl[nb][2], bl[nb][3],
                      kb + nn * 272 + (ke + 64) * 2);
            }
#pragma unroll
            for (int nf = 0; nf < 4; ++nf) {
                mma16816(sacc[nf], ah, bh[nf >> 1][(nf & 1) * 2],
                         bh[nf >> 1][(nf & 1) * 2 + 1]);
                mma16816(sacc[nf], ah, bl[nf >> 1][(nf & 1) * 2],
                         bl[nf >> 1][(nf & 1) * 2 + 1]);
                mma16816(sacc[nf], al, bh[nf >> 1][(nf & 1) * 2],
                         bh[nf >> 1][(nf & 1) * 2 + 1]);
            }
        }

        // ---- mask + scale (log2 domain) ----
#pragma unroll
        for (int nf = 0; nf < 4; ++nf) {
#pragma unroll
            for (int e = 0; e < 2; ++e) {
                int j = ks + jt * 64 + wc * 32 + nf * 8 + 2 * (lid & 3) + e;
                int d0 = j - (q0 + rlo);
                int d1 = j - (q0 + rhi);
                bool in = (j >= 0) && (j < TSEQ);
                sacc[nf][e]     = (in && d0 >= -127 && d0 <= 128)
                                  ? sacc[nf][e] * SCL : -1e30f;
                sacc[nf][2 + e] = (in && d1 >= -127 && d1 <= 128)
                                  ? sacc[nf][2 + e] * SCL : -1e30f;
            }
        }

        // ---- per-half online softmax (base-2) ----
        float mx0 = sacc[0][0], mx1 = sacc[0][2];
#pragma unroll
        for (int nf = 0; nf < 4; ++nf) {
            mx0 = fmaxf(mx0, fmaxf(sacc[nf][0], sacc[nf][1]));
            mx1 = fmaxf(mx1, fmaxf(sacc[nf][2], sacc[nf][3]));
        }
        mx0 = fmaxf(mx0, __shfl_xor_sync(0xffffffffu, mx0, 1));
        mx0 = fmaxf(mx0, __shfl_xor_sync(0xffffffffu, mx0, 2));
        mx1 = fmaxf(mx1, __shfl_xor_sync(0xffffffffu, mx1, 1));
        mx1 = fmaxf(mx1, __shfl_xor_sync(0xffffffffu, mx1, 2));
        float nm0 = fmaxf(m0, mx0);
        float nm1 = fmaxf(m1, mx1);
        float f0 = ex2(m0 - nm0);
        float f1 = ex2(m1 - nm1);
        m0 = nm0; m1 = nm1;
        sum0 *= f0; sum1 *= f1;
#pragma unroll
        for (int i = 0; i < 8; i++) {
            oacc[i][0] *= f0; oacc[i][1] *= f0;
            oacc[i][2] *= f1; oacc[i][3] *= f1;
        }

        // ---- P = 2^(S - m); fused hi/lo pack ----
        uint32_t ph[2][4], pl[2][4];
#pragma unroll
        for (int nf = 0; nf < 4; ++nf) {
            float p0 = ex2(sacc[nf][0] - nm0);
            float p1 = ex2(sacc[nf][1] - nm0);
            float p2 = ex2(sacc[nf][2] - nm1);
            float p3 = ex2(sacc[nf][3] - nm1);
            sum0 += p0 + p1;
            sum1 += p2 + p3;
            int b = nf >> 1;
            int o = (nf & 1) * 2;
            pack_hl(p0, p1, ph[b][o], pl[b][o]);
            pack_hl(p2, p3, ph[b][o + 1], pl[b][o + 1]);
        }

        // ---- O += Pcat · Vcat ----
        const uint32_t vb = sb + AV_OFF(st);
#pragma unroll
        for (int b = 0; b < 2; ++b) {
            int kcol = wc * 32 + b * 16;
            uint32_t v[4][4];
#pragma unroll
            for (int dnb = 0; dnb < 4; ++dnb) {
                int nn = dnb * 16 + (lid & 7) + ((lid >> 4) & 1) * 8;
                int kk = kcol + (((lid >> 3) & 1) << 3);
                ldsm4(v[dnb][0], v[dnb][1], v[dnb][2], v[dnb][3],
                      vb + nn * 272 + kk * 2);          // V hi
            }
#pragma unroll
            for (int n8 = 0; n8 < 8; ++n8) {
                mma16816(oacc[n8], ph[b], v[n8 >> 1][(n8 & 1) * 2],
                         v[n8 >> 1][(n8 & 1) * 2 + 1]);
                mma16816(oacc[n8], pl[b], v[n8 >> 1][(n8 & 1) * 2],
                         v[n8 >> 1][(n8 & 1) * 2 + 1]);
            }
#pragma unroll
            for (int dnb = 0; dnb < 4; ++dnb) {
                int nn = dnb * 16 + (lid & 7) + ((lid >> 4) & 1) * 8;
                int kk = kcol + (((lid >> 3) & 1) << 3);
                ldsm4(v[dnb][0], v[dnb][1], v[dnb][2], v[dnb][3],
                      vb + nn * 272 + 128 + kk * 2);    // V lo
            }
#pragma unroll
            for (int n8 = 0; n8 < 8; ++n8)
                mma16816(oacc[n8], ph[b], v[n8 >> 1][(n8 & 1) * 2],
                         v[n8 >> 1][(n8 & 1) * 2 + 1]);
        }
        __syncthreads();
    }
#undef ISSUE_KV

    // ---- merge halves (base-2), normalize, write [hi|lo] rows ----
    sum0 += __shfl_xor_sync(0xffffffffu, sum0, 1);
    sum0 += __shfl_xor_sync(0xffffffffu, sum0, 2);
    sum1 += __shfl_xor_sync(0xffffffffu, sum1, 1);
    sum1 += __shfl_xor_sync(0xffffffffu, sum1, 2);
    if ((lid & 3) == 0) {
        sSum[wc * 64 + rlo] = sum0;
        sSum[wc * 64 + rhi] = sum1;
        sM[wc * 64 + rlo] = m0;
        sM[wc * 64 + rhi] = m1;
    }
    if (wc == 1) {
#pragma unroll
        for (int i = 0; i < 8; i++) {
            int d = i * 8 + 2 * (lid & 3);
            sO[rlo * 64 + d] = oacc[i][0];
            sO[rlo * 64 + d + 1] = oacc[i][1];
            sO[rhi * 64 + d] = oacc[i][2];
            sO[rhi * 64 + d + 1] = oacc[i][3];
        }
    }
    __syncthreads();
    if (wc == 0) {
        float mo0 = sM[64 + rlo], mo1 = sM[64 + rhi];
        float M0 = fmaxf(m0, mo0), M1 = fmaxf(m1, mo1);
        float fs0 = ex2(m0 - M0), fo0 = ex2(mo0 - M0);
        float fs1 = ex2(m1 - M1), fo1 = ex2(mo1 - M1);
        float inv0 = 1.f / (sSum[rlo] * fs0 + sSum[64 + rlo] * fo0);
        float inv1 = 1.f / (sSum[rhi] * fs1 + sSum[64 + rhi] * fo1);
        __nv_bfloat16* outLo = g_acat + ((size_t)(n * TSEQ) + q0 + rlo) * GKD + h * HD;
        __nv_bfloat16* outHi = g_acat + ((size_t)(n * TSEQ) + q0 + rhi) * GKD + h * HD;
#pragma unroll
        for (int i = 0; i < 8; i++) {
            int d = i * 8 + 2 * (lid & 3);
            float v0 = (oacc[i][0] * fs0 + sO[rlo * 64 + d] * fo0) * inv0;
            float v1 = (oacc[i][1] * fs0 + sO[rlo * 64 + d + 1] * fo0) * inv0;
            float v2 = (oacc[i][2] * fs1 + sO[rhi * 64 + d] * fo1) * inv1;
            float v3 = (oacc[i][3] * fs1 + sO[rhi * 64 + d + 1] * fo1) * inv1;
            uint32_t h01, l01, h23, l23;
            pack_hl(v0, v1, h01, l01);
            pack_hl(v2, v3, h23, l23);
            *(uint32_t*)(outLo + d)       = h01;
            *(uint32_t*)(outLo + d + 512) = l01;
            *(uint32_t*)(outHi + d)       = h23;
            *(uint32_t*)(outHi + d + 512) = l23;
        }
    }
}

// ---------------- launcher ---------------------------------------------------
extern "C" void kernel_launch(void* const* d_in, const int* in_sizes, int n_in,
                              void* d_out, int out_size) {
    (void)in_sizes; (void)n_in; (void)out_size;
    const float* x    = (const float*)d_in[0];
    const float* Wqkv = (const float*)d_in[1];
    const float* Wout = (const float*)d_in[2];
    const float* bout = (const float*)d_in[3];
    float* out = (float*)d_out;

    float* qkv_ptr = nullptr;
    cudaGetSymbolAddress((void**)&qkv_ptr, g_qkv);
    __nv_bfloat16 *xcat, *acat, *wqcat, *wocat;
    cudaGetSymbolAddress((void**)&xcat, g_xcat);
    cudaGetSymbolAddress((void**)&acat, g_acat);
    cudaGetSymbolAddress((void**)&wqcat, g_wqcat);
    cudaGetSymbolAddress((void**)&wocat, g_wocat);

    cudaFuncSetAttribute(attn_flash_kernel,
                         cudaFuncAttributeMaxDynamicSharedMemorySize,
                         AFL_SMEM);

    rope_table_kernel<<<(TSEQ * 32 + 255) / 256, 256>>>();

    split_kernel<<<(MTOT * 128 + 255) / 256, 256>>>(x, xcat, MTOT * 128);
    split_kernel<<<(EQKV * 128 + 255) / 256, 256>>>(Wqkv, wqcat, EQKV * 128);
    split_kernel<<<(DM * 128 + 255) / 256, 256>>>(Wout, wocat, DM * 128);

    // qkv = x @ Wqkv^T  (split-bf16 HMMA, de-duplicated operands)
    gemm_mma<false><<<dim3(EQKV / 128, MTOT / 128), 256>>>(
        xcat, wqcat, nullptr, qkv_ptr, EQKV);

    // fused RoPE + V transpose
    prep_kernel<<<dim3(TSEQ / 32, NB * NH), 256>>>();

    // attention (dedup Q/K) writes [hi|lo] operand rows directly
    attn_flash_kernel<<<dim3(TSEQ / QT, NB * NH), 256, AFL_SMEM>>>();

    // out = attn @ Wout^T + bout
    gemm_mma<true><<<dim3(DM / 128, MTOT / 128), 256>>>(
        acat, wocat, bout, out, DM);
}